// round 14
// baseline (speedup 1.0000x reference)
#include <cuda_runtime.h>
#include <cuda_bf16.h>
#include <cstdint>
#include <math.h>

#define SQ   1024
#define DM   1024
#define NH   16
#define DKH  64
#define BSZ  2
#define MROWS (BSZ*SQ)

typedef uint32_t u32;

// ---------------------------------------------------------------------------
// Device scratch
// ---------------------------------------------------------------------------
__device__ __nv_bfloat16 g_Wth[4][DM*DM];  // W^T hi (K-major [n][k])
__device__ __nv_bfloat16 g_Wtl[4][DM*DM];  // W^T lo
__device__ float g_P[2][MROWS*DM];         // projected Q,K
__device__ float g_Vt[BSZ*NH*DKH*SQ];      // projected V, transposed [b,h,d,S]
__device__ float g_O[MROWS*DM];            // attention output

__constant__ int   c_SRC[16] = {0,1,2,3,  1,0,3,2,  2,3,0,1,  3,2,1,0};
__constant__ float c_SGN[16] = {1.f,1.f,1.f,1.f,  -1.f,1.f,-1.f,1.f,
                                -1.f,1.f,1.f,-1.f, -1.f,-1.f,1.f,1.f};

struct WPtrs { const float* w[16]; };
struct GemmArgs { const float* A[3]; const float* bias[3]; };

#define BFPACK(r, flo, fhi) \
    asm("cvt.rn.bf16x2.f32 %0, %1, %2;" : "=r"(r) : "f"(fhi), "f"(flo))

#define HMMA(c, a0, a1, a2, a3, b0, b1) \
    asm volatile("mma.sync.aligned.m16n8k16.row.col.f32.bf16.bf16.f32 " \
        "{%0,%1,%2,%3}, {%4,%5,%6,%7}, {%8,%9}, {%0,%1,%2,%3};" \
        : "+f"((c)[0]), "+f"((c)[1]), "+f"((c)[2]), "+f"((c)[3]) \
        : "r"(a0), "r"(a1), "r"(a2), "r"(a3), "r"(b0), "r"(b1))

#define SGNM 0x80008000u

// ---------------------------------------------------------------------------
__global__ __launch_bounds__(256)
void build_wbig_kernel(WPtrs p) {
    __shared__ float s[32][33];
    int tx = threadIdx.x & 31, ty = threadIdx.x >> 5;
    int k0 = blockIdx.x * 32, n0 = blockIdx.y * 32, which = blockIdx.z;
    int rb = k0 >> 8, cb = n0 >> 8;
    float sgn = c_SGN[rb * 4 + cb];
    const float* src = p.w[which * 4 + c_SRC[rb * 4 + cb]];
#pragma unroll
    for (int i = 0; i < 4; i++) {
        int kl = ty + i * 8;
        s[kl][tx] = sgn * src[((k0 + kl) & 255) * 256 + ((n0 + tx) & 255)];
    }
    __syncthreads();
#pragma unroll
    for (int i = 0; i < 4; i++) {
        int nl = ty + i * 8;
        float v = s[tx][nl];
        __nv_bfloat16 hi = __float2bfloat16_rn(v);
        __nv_bfloat16 lo = __float2bfloat16_rn(v - __bfloat162float(hi));
        size_t o = (size_t)(n0 + nl) * DM + k0 + tx;
        g_Wth[which][o] = hi;
        g_Wtl[which][o] = lo;
    }
}

// ---------------------------------------------------------------------------
// Tensor-core GEMM: 128x64 C-tile, double-buffered, true 2 CTAs/SM.
// 8 warps = 2(m:64 rows) x 4(n:16 cols); warp tile 64x16; k-chunk 32.
// ---------------------------------------------------------------------------
#define KCP 40
#define GSTA (128 * KCP)                 // A hi or lo tile elements
#define GSTW (64 * KCP)                  // W hi or lo tile elements
#define STEL (2 * GSTA + 2 * GSTW)       // elements per stage = 15360
#define GEMM_SMEM_BYTES (2 * STEL * 2)   // 61440 B

__device__ __forceinline__
void gemm_store_stage(__nv_bfloat16* base, int tid,
                      const float4 aR[4], const uint4 whR, const uint4 wlR)
{
    __nv_bfloat16* Ah_s = base;
    __nv_bfloat16* Al_s = base + GSTA;
    __nv_bfloat16* Wh_s = base + 2 * GSTA;
    __nv_bfloat16* Wl_s = base + 2 * GSTA + GSTW;
#pragma unroll
    for (int i = 0; i < 4; i++) {
        int idx = tid + i * 256;
        int r = idx >> 3, c4 = (idx & 7) * 4;
        float4 a = aR[i];
        u32 h01, h23, l01, l23;
        BFPACK(h01, a.x, a.y);
        BFPACK(h23, a.z, a.w);
        float rx = a.x - __uint_as_float(h01 << 16);
        float ry = a.y - __uint_as_float(h01 & 0xffff0000u);
        float rz = a.z - __uint_as_float(h23 << 16);
        float rw = a.w - __uint_as_float(h23 & 0xffff0000u);
        BFPACK(l01, rx, ry);
        BFPACK(l23, rz, rw);
        int so = r * KCP + c4;
        *(uint2*)(Ah_s + so) = make_uint2(h01, h23);
        *(uint2*)(Al_s + so) = make_uint2(l01, l23);
    }
    {
        int r = tid >> 2, c8 = (tid & 3) * 8;   // 64 rows x 4 uint4
        int so = r * KCP + c8;
        *(uint4*)(Wh_s + so) = whR;
        *(uint4*)(Wl_s + so) = wlR;
    }
}

__device__ __forceinline__
void tc_gemm_body(__nv_bfloat16* gsm, const float* __restrict__ A,
                  const __nv_bfloat16* __restrict__ Wh,
                  const __nv_bfloat16* __restrict__ Wl,
                  const float* __restrict__ bias, float* __restrict__ C, int vt)
{
    int tid = threadIdx.x;
    int wid = tid >> 5, lane = tid & 31;
    int gid = lane >> 2, tig = lane & 3;
    int wm = wid & 1, wn = wid >> 1;         // 2 x 4 warps
    int m0 = blockIdx.y * 128, n0 = blockIdx.x * 64;

    float acc[4][2][4];
#pragma unroll
    for (int mi = 0; mi < 4; mi++)
#pragma unroll
        for (int ni = 0; ni < 2; ni++)
#pragma unroll
            for (int j = 0; j < 4; j++) acc[mi][ni][j] = 0.f;

    int wr = tid >> 2, wc8 = (tid & 3) * 8;  // W load coords (64 x 4 uint4)

    float4 aR[4]; uint4 whR, wlR;
    {
        const float* Ar = A + (size_t)m0 * DM;
#pragma unroll
        for (int i = 0; i < 4; i++) {
            int idx = tid + i * 256;
            int r = idx >> 3, c4 = (idx & 7) * 4;
            aR[i] = *(const float4*)(Ar + (size_t)r * DM + c4);
        }
        size_t go = (size_t)(n0 + wr) * DM + wc8;
        whR = *(const uint4*)(Wh + go);
        wlR = *(const uint4*)(Wl + go);
    }
    gemm_store_stage(gsm, tid, aR, whR, wlR);
    __syncthreads();

    for (int kt = 0; kt < 32; kt++) {
        if (kt < 31) {
            int k0n = (kt + 1) * 32;
            const float* Ar = A + (size_t)m0 * DM + k0n;
#pragma unroll
            for (int i = 0; i < 4; i++) {
                int idx = tid + i * 256;
                int r = idx >> 3, c4 = (idx & 7) * 4;
                aR[i] = *(const float4*)(Ar + (size_t)r * DM + c4);
            }
            size_t go = (size_t)(n0 + wr) * DM + k0n + wc8;
            whR = *(const uint4*)(Wh + go);
            wlR = *(const uint4*)(Wl + go);
        }

        __nv_bfloat16* st = gsm + (size_t)(kt & 1) * STEL;
        __nv_bfloat16* Ah_s = st;
        __nv_bfloat16* Al_s = st + GSTA;
        __nv_bfloat16* Wh_s = st + 2 * GSTA;
        __nv_bfloat16* Wl_s = st + 2 * GSTA + GSTW;

#pragma unroll
        for (int ks = 0; ks < 2; ks++) {
            int kb = ks * 16 + tig * 2;
            u32 bh[2][2], bl[2][2];
#pragma unroll
            for (int ni = 0; ni < 2; ni++) {
                int n = wn * 16 + ni * 8 + gid;
                int off = n * KCP + kb;
                bh[ni][0] = *(const u32*)(Wh_s + off);
                bh[ni][1] = *(const u32*)(Wh_s + off + 8);
                bl[ni][0] = *(const u32*)(Wl_s + off);
                bl[ni][1] = *(const u32*)(Wl_s + off + 8);
            }
#pragma unroll
            for (int mi = 0; mi < 4; mi++) {
                int r = wm * 64 + mi * 16 + gid;
                int off = r * KCP + kb;
                u32 ah0 = *(const u32*)(Ah_s + off);
                u32 ah1 = *(const u32*)(Ah_s + off + 8 * KCP);
                u32 ah2 = *(const u32*)(Ah_s + off + 8);
                u32 ah3 = *(const u32*)(Ah_s + off + 8 * KCP + 8);
                u32 al0 = *(const u32*)(Al_s + off);
                u32 al1 = *(const u32*)(Al_s + off + 8 * KCP);
                u32 al2 = *(const u32*)(Al_s + off + 8);
                u32 al3 = *(const u32*)(Al_s + off + 8 * KCP + 8);
#pragma unroll
                for (int ni = 0; ni < 2; ni++) {
                    HMMA(acc[mi][ni], ah0, ah1, ah2, ah3, bh[ni][0], bh[ni][1]);
                    HMMA(acc[mi][ni], ah0, ah1, ah2, ah3, bl[ni][0], bl[ni][1]);
                    HMMA(acc[mi][ni], al0, al1, al2, al3, bh[ni][0], bh[ni][1]);
                }
            }
        }
        if (kt < 31)
            gemm_store_stage(gsm + (size_t)((kt + 1) & 1) * STEL, tid, aR, whR, wlR);
        __syncthreads();
    }

#pragma unroll
    for (int mi = 0; mi < 4; mi++) {
        int r = m0 + wm * 64 + mi * 16 + gid;
#pragma unroll
        for (int ni = 0; ni < 2; ni++) {
            int c = n0 + wn * 16 + ni * 8 + tig * 2;
            float b0 = bias[c], b1 = bias[c + 1];
            if (!vt) {
                *(float2*)(C + (size_t)r * DM + c) =
                    make_float2(acc[mi][ni][0] + b0, acc[mi][ni][1] + b1);
                *(float2*)(C + (size_t)(r + 8) * DM + c) =
                    make_float2(acc[mi][ni][2] + b0, acc[mi][ni][3] + b1);
            } else {
                int b = r >> 10, s = r & 1023;
                int h = c >> 6, d = c & 63;
                float* base = g_Vt + ((size_t)(b * NH + h) * DKH) * SQ;
                base[(size_t)d * SQ + s]           = acc[mi][ni][0] + b0;
                base[(size_t)(d + 1) * SQ + s]     = acc[mi][ni][1] + b1;
                base[(size_t)d * SQ + s + 8]       = acc[mi][ni][2] + b0;
                base[(size_t)(d + 1) * SQ + s + 8] = acc[mi][ni][3] + b1;
            }
        }
    }
}

__global__ __launch_bounds__(256, 2)
void qkv_gemm_kernel(GemmArgs args) {
    extern __shared__ __nv_bfloat16 gsm[];
    int z = blockIdx.z;
    tc_gemm_body(gsm, args.A[z], g_Wth[z], g_Wtl[z], args.bias[z],
                 z < 2 ? g_P[z] : nullptr, z == 2);
}
__global__ __launch_bounds__(256, 2)
void o_gemm_kernel(const float* __restrict__ bias, float* __restrict__ Cout) {
    extern __shared__ __nv_bfloat16 gsm[];
    tc_gemm_body(gsm, g_O, g_Wth[3], g_Wtl[3], bias, Cout, 0);
}

// ---------------------------------------------------------------------------
// Tensor-core quaternion flash attention (R13 known-good version).
// ---------------------------------------------------------------------------
#define STR 72
#define TILE_B (64*STR)

#define S_QH  0
#define S_QL  (S_QH + TILE_B)
#define S_KH  (S_QL + TILE_B)
#define S_KL  (S_KH + TILE_B)
#define S_VH  (S_KL + TILE_B)
#define S_VL  (S_VH + TILE_B)
#define S_PH  (S_VL + TILE_B)           // [4][64][STR]
#define S_PL  (S_PH + 4*TILE_B)
#define S_END (S_PL + 4*TILE_B)
#define ATT_SMEM_BYTES (S_END*2 + 4*64*2*8 + 256)

__device__ __forceinline__
void kv_store_one(__nv_bfloat16* sm, int hioff, int looff, int so, float4 a)
{
    u32 h01, h23, l01, l23;
    BFPACK(h01, a.x, a.y);
    BFPACK(h23, a.z, a.w);
    float rx = a.x - __uint_as_float(h01 << 16);
    float ry = a.y - __uint_as_float(h01 & 0xffff0000u);
    float rz = a.z - __uint_as_float(h23 << 16);
    float rw = a.w - __uint_as_float(h23 & 0xffff0000u);
    BFPACK(l01, rx, ry);
    BFPACK(l23, rz, rw);
    *(uint2*)(sm + hioff + so) = make_uint2(h01, h23);
    *(uint2*)(sm + looff + so) = make_uint2(l01, l23);
}

__global__ __launch_bounds__(256, 1)
void quat_attn_tc_kernel(const int* __restrict__ mask)
{
    extern __shared__ __nv_bfloat16 sm[];
    float2* stats2 = (float2*)(sm + S_END);     // [4][64][2] (max, expsum)
    int*    msk    = (int*)(stats2 + 4 * 64 * 2);

    const int tsrc[4][4] = {{0,1,2,3},{1,0,3,2},{2,3,0,1},{3,2,1,0}};
    const int tsgn[4][4] = {{1,1,1,1},{-1,1,-1,1},{-1,1,1,-1},{-1,-1,1,1}};

    int tid = threadIdx.x;
    int wid = tid >> 5, lane = tid & 31;
    int gid = lane >> 2, tig = lane & 3;
    int mtile = wid >> 1, wh = wid & 1;
    int m16 = mtile * 16;
    int bh = blockIdx.y;
    int b = bh >> 4, h = bh & 15;
    int q0 = blockIdx.x * 64;

    const float* Qg = g_P[0] + (size_t)(b * SQ) * DM + h * DKH;
    const float* Kg = g_P[1] + (size_t)(b * SQ) * DM + h * DKH;
    const float* Vg = g_Vt + (size_t)bh * DKH * SQ;
    const int*   mrow = mask + b * SQ;

    int ldr = tid >> 4, ldc = (tid & 15) * 4;

    // ---- load Q tile (scaled by 1/8) ----
#pragma unroll
    for (int i = 0; i < 4; i++) {
        int r = ldr + i * 16;
        float4 a = *(const float4*)(Qg + (size_t)(q0 + r) * DM + ldc);
        a.x *= 0.125f; a.y *= 0.125f; a.z *= 0.125f; a.w *= 0.125f;
        kv_store_one(sm, S_QH, S_QL, r * STR + ldc, a);
    }
    __syncthreads();

    // ---- persistent Q fragments ----
    u32 qfh[4][4], qfl[4][4];
#pragma unroll
    for (int u = 0; u < 4; u++) {
        int off = (m16 + gid) * STR + u * 16 + tig * 2;
        qfh[u][0] = *(const u32*)(sm + S_QH + off);
        qfh[u][1] = *(const u32*)(sm + S_QH + off + 8 * STR);
        qfh[u][2] = *(const u32*)(sm + S_QH + off + 8);
        qfh[u][3] = *(const u32*)(sm + S_QH + off + 8 * STR + 8);
        qfl[u][0] = *(const u32*)(sm + S_QL + off);
        qfl[u][1] = *(const u32*)(sm + S_QL + off + 8 * STR);
        qfl[u][2] = *(const u32*)(sm + S_QL + off + 8);
        qfl[u][3] = *(const u32*)(sm + S_QL + off + 8 * STR + 8);
    }

    float mrun[4][2], lrun[4][2];
    float U[4][4][4];
#pragma unroll
    for (int c = 0; c < 4; c++) {
#pragma unroll
        for (int j = 0; j < 2; j++) { mrun[c][j] = -1e30f; lrun[c][j] = 0.f; }
#pragma unroll
        for (int nt = 0; nt < 4; nt++)
#pragma unroll
            for (int j = 0; j < 4; j++) U[c][nt][j] = 0.f;
    }

    float4 kR[4], vR[4];
#pragma unroll
    for (int i = 0; i < 4; i++) {
        int r = ldr + i * 16;
        kR[i] = *(const float4*)(Kg + (size_t)r * DM + ldc);
        vR[i] = *(const float4*)(Vg + (size_t)r * SQ + ldc);
    }
#pragma unroll
    for (int i = 0; i < 4; i++) {
        int r = ldr + i * 16;
        kv_store_one(sm, S_KH, S_KL, r * STR + ldc, kR[i]);
        kv_store_one(sm, S_VH, S_VL, r * STR + ldc, vR[i]);
    }
    if (tid < 64) msk[tid] = mrow[tid];
    __syncthreads();

    for (int t = 0; t < 16; t++) {
        int n0 = t * 64;
        if (t < 15) {
            int n1 = n0 + 64;
#pragma unroll
            for (int i = 0; i < 4; i++) {
                int r = ldr + i * 16;
                kR[i] = *(const float4*)(Kg + (size_t)(n1 + r) * DM + ldc);
                vR[i] = *(const float4*)(Vg + (size_t)r * SQ + n1 + ldc);
            }
        }

        // ---- score MMAs ----
        float sc[4][4][4];
#pragma unroll
        for (int c = 0; c < 4; c++)
#pragma unroll
            for (int nt = 0; nt < 4; nt++)
#pragma unroll
                for (int j = 0; j < 4; j++) sc[c][nt][j] = 0.f;

#pragma unroll
        for (int nt = 0; nt < 4; nt++) {
            int kb0 = wh * 32 + nt * 8;
            u32 kf[4][2][2];
#pragma unroll
            for (int comp = 0; comp < 4; comp++) {
                int off = (kb0 + gid) * STR + comp * 16 + tig * 2;
                kf[comp][0][0] = *(const u32*)(sm + S_KH + off);
                kf[comp][0][1] = *(const u32*)(sm + S_KH + off + 8);
                kf[comp][1][0] = *(const u32*)(sm + S_KL + off);
                kf[comp][1][1] = *(const u32*)(sm + S_KL + off + 8);
            }
#pragma unroll
            for (int c = 0; c < 4; c++)
#pragma unroll
                for (int u = 0; u < 4; u++) {
                    int src = tsrc[u][c];
                    u32 bh0 = kf[src][0][0], bh1 = kf[src][0][1];
                    u32 bl0 = kf[src][1][0], bl1 = kf[src][1][1];
                    if (tsgn[u][c] < 0) {
                        bh0 ^= SGNM; bh1 ^= SGNM; bl0 ^= SGNM; bl1 ^= SGNM;
                    }
                    HMMA(sc[c][nt], qfh[u][0], qfh[u][1], qfh[u][2], qfh[u][3], bh0, bh1);
                    HMMA(sc[c][nt], qfh[u][0], qfh[u][1], qfh[u][2], qfh[u][3], bl0, bl1);
                    HMMA(sc[c][nt], qfl[u][0], qfl[u][1], qfl[u][2], qfl[u][3], bh0, bh1);
                }
        }

        // ---- mask ----
#pragma unroll
        for (int nt = 0; nt < 4; nt++) {
            int kb0 = wh * 32 + nt * 8 + tig * 2;
            int m0v = msk[kb0], m1v = msk[kb0 + 1];
#pragma unroll
            for (int c = 0; c < 4; c++) {
                if (!m0v) { sc[c][nt][0] = -1e9f; sc[c][nt][2] = -1e9f; }
                if (!m1v) { sc[c][nt][1] = -1e9f; sc[c][nt][3] = -1e9f; }
            }
        }

        // ---- per-warp tile softmax, single exchange ----
        float tmx[4][2], tsum[4][2];
#pragma unroll
        for (int c = 0; c < 4; c++) {
            float t0 = -1e30f, t1 = -1e30f;
#pragma unroll
            for (int nt = 0; nt < 4; nt++) {
                t0 = fmaxf(t0, fmaxf(sc[c][nt][0], sc[c][nt][1]));
                t1 = fmaxf(t1, fmaxf(sc[c][nt][2], sc[c][nt][3]));
            }
            t0 = fmaxf(t0, __shfl_xor_sync(0xffffffffu, t0, 1));
            t0 = fmaxf(t0, __shfl_xor_sync(0xffffffffu, t0, 2));
            t1 = fmaxf(t1, __shfl_xor_sync(0xffffffffu, t1, 1));
            t1 = fmaxf(t1, __shfl_xor_sync(0xffffffffu, t1, 2));
            float s0 = 0.f, s1 = 0.f;
#pragma unroll
            for (int nt = 0; nt < 4; nt++) {
                sc[c][nt][0] = __expf(sc[c][nt][0] - t0);
                sc[c][nt][1] = __expf(sc[c][nt][1] - t0);
                sc[c][nt][2] = __expf(sc[c][nt][2] - t1);
                sc[c][nt][3] = __expf(sc[c][nt][3] - t1);
                s0 += sc[c][nt][0] + sc[c][nt][1];
                s1 += sc[c][nt][2] + sc[c][nt][3];
            }
            s0 += __shfl_xor_sync(0xffffffffu, s0, 1);
            s0 += __shfl_xor_sync(0xffffffffu, s0, 2);
            s1 += __shfl_xor_sync(0xffffffffu, s1, 1);
            s1 += __shfl_xor_sync(0xffffffffu, s1, 2);
            tmx[c][0] = t0; tmx[c][1] = t1;
            tsum[c][0] = s0; tsum[c][1] = s1;
            if (tig == 0) {
                stats2[(c * 64 + m16 + gid) * 2 + wh] = make_float2(t0, s0);
                stats2[(c * 64 + m16 + gid + 8) * 2 + wh] = make_float2(t1, s1);
            }
        }
        __syncthreads();

        // ---- merge with partner half, rescale U, pack scaled P ----
#pragma unroll
        for (int c = 0; c < 4; c++) {
            float2 o0 = stats2[(c * 64 + m16 + gid) * 2 + (wh ^ 1)];
            float2 o1 = stats2[(c * 64 + m16 + gid + 8) * 2 + (wh ^ 1)];
            float mn0 = fmaxf(mrun[c][0], fmaxf(tmx[c][0], o0.x));
            float mn1 = fmaxf(mrun[c][1], fmaxf(tmx[c][1], o1.x));
            float corr0 = __expf(mrun[c][0] - mn0);
            float corr1 = __expf(mrun[c][1] - mn1);
            float f0 = __expf(tmx[c][0] - mn0);
            float f1 = __expf(tmx[c][1] - mn1);
            float g0 = __expf(o0.x - mn0);
            float g1 = __expf(o1.x - mn1);
            lrun[c][0] = lrun[c][0] * corr0 + tsum[c][0] * f0 + o0.y * g0;
            lrun[c][1] = lrun[c][1] * corr1 + tsum[c][1] * f1 + o1.y * g1;
            mrun[c][0] = mn0; mrun[c][1] = mn1;
#pragma unroll
            for (int nt = 0; nt < 4; nt++) {
                U[c][nt][0] *= corr0;
                U[c][nt][1] *= corr0;
                U[c][nt][2] *= corr1;
                U[c][nt][3] *= corr1;
            }
#pragma unroll
            for (int nt = 0; nt < 4; nt++) {
                int key = wh * 32 + nt * 8 + tig * 2;
                float p0 = sc[c][nt][0] * f0, p1 = sc[c][nt][1] * f0;
                u32 h01, l01;
                BFPACK(h01, p0, p1);
                float rx = p0 - __uint_as_float(h01 << 16);
                float ry = p1 - __uint_as_float(h01 & 0xffff0000u);
                BFPACK(l01, rx, ry);
                int ro = (c * 64 + m16 + gid) * STR + key;
                *(u32*)(sm + S_PH + ro) = h01;
                *(u32*)(sm + S_PL + ro) = l01;
                float p2 = sc[c][nt][2] * f1, p3 = sc[c][nt][3] * f1;
                BFPACK(h01, p2, p3);
                rx = p2 - __uint_as_float(h01 << 16);
                ry = p3 - __uint_as_float(h01 & 0xffff0000u);
                BFPACK(l01, rx, ry);
                ro = (c * 64 + m16 + gid + 8) * STR + key;
                *(u32*)(sm + S_PH + ro) = h01;
                *(u32*)(sm + S_PL + ro) = l01;
            }
        }
        __syncthreads();

        // ---- PV MMAs ----
#pragma unroll
        for (int c = 0; c < 4; c++) {
#pragma unroll
            for (int u = 0; u < 4; u++) {
                int ao = (c * 64 + m16 + gid) * STR + u * 16 + tig * 2;
                u32 pa0 = *(const u32*)(sm + S_PH + ao);
                u32 pa1 = *(const u32*)(sm + S_PH + ao + 8 * STR);
                u32 pa2 = *(const u32*)(sm + S_PH + ao + 8);
                u32 pa3 = *(const u32*)(sm + S_PH + ao + 8 * STR + 8);
                u32 la0 = *(const u32*)(sm + S_PL + ao);
                u32 la1 = *(const u32*)(sm + S_PL + ao + 8 * STR);
                u32 la2 = *(const u32*)(sm + S_PL + ao + 8);
                u32 la3 = *(const u32*)(sm + S_PL + ao + 8 * STR + 8);
#pragma unroll
                for (int nt = 0; nt < 4; nt++) {
                    int oc = wh * 2 + (nt >> 1);
                    int src = tsrc[c][oc];
                    u32 smask = (tsgn[c][oc] < 0) ? SGNM : 0u;
                    int bo = (src * 16 + (nt & 1) * 8 + gid) * STR + u * 16 + tig * 2;
                    u32 vh0 = *(const u32*)(sm + S_VH + bo) ^ smask;
                    u32 vh1 = *(const u32*)(sm + S_VH + bo + 8) ^ smask;
                    u32 vl0 = *(const u32*)(sm + S_VL + bo) ^ smask;
                    u32 vl1 = *(const u32*)(sm + S_VL + bo + 8) ^ smask;
                    HMMA(U[c][nt], pa0, pa1, pa2, pa3, vh0, vh1);
                    HMMA(U[c][nt], pa0, pa1, pa2, pa3, vl0, vl1);
                    HMMA(U[c][nt], la0, la1, la2, la3, vh0, vh1);
                }
            }
        }
        __syncthreads();   // PV reads done before K/V overwrite

        if (t < 15) {
#pragma unroll
            for (int i = 0; i < 4; i++) {
                int r = ldr + i * 16;
                kv_store_one(sm, S_KH, S_KL, r * STR + ldc, kR[i]);
                kv_store_one(sm, S_VH, S_VL, r * STR + ldc, vR[i]);
            }
            if (tid < 64) msk[tid] = mrow[n0 + 64 + tid];
            __syncthreads();
        }
    }

    // ---- register epilogue ----
    float inv[4][2];
#pragma unroll
    for (int c = 0; c < 4; c++) {
        inv[c][0] = 1.f / lrun[c][0];
        inv[c][1] = 1.f / lrun[c][1];
    }
    float* Og = g_O + (size_t)(b * SQ) * DM + h * DKH;
    int r0 = q0 + m16 + gid;
#pragma unroll
    for (int nt = 0; nt < 4; nt++) {
        int col = wh * 32 + nt * 8 + tig * 2;
        float o0 = 0.f, o1 = 0.f, o2 = 0.f, o3 = 0.f;
#pragma unroll
        for (int c = 0; c < 4; c++) {
            o0 += U[c][nt][0] * inv[c][0];
            o1 += U[c][nt][1] * inv[c][0];
            o2 += U[c][nt][2] * inv[c][1];
            o3 += U[c][nt][3] * inv[c][1];
        }
        *(float2*)(Og + (size_t)r0 * DM + col) = make_float2(o0, o1);
        *(float2*)(Og + (size_t)(r0 + 8) * DM + col) = make_float2(o2, o3);
    }
}

// ---------------------------------------------------------------------------
extern "C" void kernel_launch(void* const* d_in, const int* in_sizes, int n_in,
                              void* d_out, int out_size)
{
    (void)in_sizes; (void)n_in; (void)out_size;
    // 0 q, 1 k, 2 v, 3 mask, 4-19 weights, 20 bq, 21 bk, 22 bv, 23 bo
    WPtrs wp;
    for (int i = 0; i < 16; i++) wp.w[i] = (const float*)d_in[4 + i];

    build_wbig_kernel<<<dim3(32, 32, 4), 256>>>(wp);

    GemmArgs ga;
    for (int z = 0; z < 3; z++) {
        ga.A[z]    = (const float*)d_in[z];
        ga.bias[z] = (const float*)d_in[20 + z];
    }
    cudaFuncSetAttribute(qkv_gemm_kernel,
                         cudaFuncAttributeMaxDynamicSharedMemorySize, GEMM_SMEM_BYTES);
    cudaFuncSetAttribute(o_gemm_kernel,
                         cudaFuncAttributeMaxDynamicSharedMemorySize, GEMM_SMEM_BYTES);

    dim3 qkvgrid(DM / 64, MROWS / 128, 3);    // (16, 16, 3)
    qkv_gemm_kernel<<<qkvgrid, 256, GEMM_SMEM_BYTES>>>(ga);

    cudaFuncSetAttribute(quat_attn_tc_kernel,
                         cudaFuncAttributeMaxDynamicSharedMemorySize, ATT_SMEM_BYTES);
    quat_attn_tc_kernel<<<dim3(SQ / 64, BSZ * NH), 256, ATT_SMEM_BYTES>>>(
        (const int*)d_in[3]);

    dim3 ogrid(DM / 64, MROWS / 128);         // (16, 16)
    o_gemm_kernel<<<ogrid, 256, GEMM_SMEM_BYTES>>>((const float*)d_in[23], (float*)d_out);
}

// round 15
// speedup vs baseline: 1.0283x; 1.0283x over previous
#include <cuda_runtime.h>
#include <cuda_bf16.h>
#include <cstdint>
#include <math.h>

#define SQ   1024
#define DM   1024
#define NH   16
#define DKH  64
#define BSZ  2
#define MROWS (BSZ*SQ)

typedef uint32_t u32;

// ---------------------------------------------------------------------------
// Device scratch
// ---------------------------------------------------------------------------
__device__ __nv_bfloat16 g_Wth[4][DM*DM];  // W^T hi (K-major [n][k])
__device__ __nv_bfloat16 g_Wtl[4][DM*DM];  // W^T lo
__device__ float g_P[2][MROWS*DM];         // projected Q,K
__device__ float g_Vt[BSZ*NH*DKH*SQ];      // projected V, transposed [b,h,d,S]
__device__ float g_O[MROWS*DM];            // attention output

__constant__ int   c_SRC[16] = {0,1,2,3,  1,0,3,2,  2,3,0,1,  3,2,1,0};
__constant__ float c_SGN[16] = {1.f,1.f,1.f,1.f,  -1.f,1.f,-1.f,1.f,
                                -1.f,1.f,1.f,-1.f, -1.f,-1.f,1.f,1.f};

struct WPtrs { const float* w[16]; };
struct GemmArgs { const float* A[3]; const float* bias[3]; };

#define BFPACK(r, flo, fhi) \
    asm("cvt.rn.bf16x2.f32 %0, %1, %2;" : "=r"(r) : "f"(fhi), "f"(flo))

#define HMMA(c, a0, a1, a2, a3, b0, b1) \
    asm volatile("mma.sync.aligned.m16n8k16.row.col.f32.bf16.bf16.f32 " \
        "{%0,%1,%2,%3}, {%4,%5,%6,%7}, {%8,%9}, {%0,%1,%2,%3};" \
        : "+f"((c)[0]), "+f"((c)[1]), "+f"((c)[2]), "+f"((c)[3]) \
        : "r"(a0), "r"(a1), "r"(a2), "r"(a3), "r"(b0), "r"(b1))

#define SGNM 0x80008000u

// ---------------------------------------------------------------------------
__global__ __launch_bounds__(256)
void build_wbig_kernel(WPtrs p) {
    __shared__ float s[32][33];
    int tx = threadIdx.x & 31, ty = threadIdx.x >> 5;
    int k0 = blockIdx.x * 32, n0 = blockIdx.y * 32, which = blockIdx.z;
    int rb = k0 >> 8, cb = n0 >> 8;
    float sgn = c_SGN[rb * 4 + cb];
    const float* src = p.w[which * 4 + c_SRC[rb * 4 + cb]];
#pragma unroll
    for (int i = 0; i < 4; i++) {
        int kl = ty + i * 8;
        s[kl][tx] = sgn * src[((k0 + kl) & 255) * 256 + ((n0 + tx) & 255)];
    }
    __syncthreads();
#pragma unroll
    for (int i = 0; i < 4; i++) {
        int nl = ty + i * 8;
        float v = s[tx][nl];
        __nv_bfloat16 hi = __float2bfloat16_rn(v);
        __nv_bfloat16 lo = __float2bfloat16_rn(v - __bfloat162float(hi));
        size_t o = (size_t)(n0 + nl) * DM + k0 + tx;
        g_Wth[which][o] = hi;
        g_Wtl[which][o] = lo;
    }
}

// ---------------------------------------------------------------------------
// Tensor-core GEMM, double-buffered (R13 known-good: 128x128, no clamp).
// ---------------------------------------------------------------------------
#define KCP 40
#define GST (128 * KCP)
#define GEMM_SMEM_BYTES (2 * 4 * GST * 2)  // 81920 B

__device__ __forceinline__
void gemm_store_stage(__nv_bfloat16* base, int tid,
                      const float4 aR[4], const uint4 whR[2], const uint4 wlR[2])
{
    __nv_bfloat16* Ah_s = base;
    __nv_bfloat16* Al_s = base + GST;
    __nv_bfloat16* Wh_s = base + 2 * GST;
    __nv_bfloat16* Wl_s = base + 3 * GST;
#pragma unroll
    for (int i = 0; i < 4; i++) {
        int idx = tid + i * 256;
        int r = idx >> 3, c4 = (idx & 7) * 4;
        float4 a = aR[i];
        u32 h01, h23, l01, l23;
        BFPACK(h01, a.x, a.y);
        BFPACK(h23, a.z, a.w);
        float rx = a.x - __uint_as_float(h01 << 16);
        float ry = a.y - __uint_as_float(h01 & 0xffff0000u);
        float rz = a.z - __uint_as_float(h23 << 16);
        float rw = a.w - __uint_as_float(h23 & 0xffff0000u);
        BFPACK(l01, rx, ry);
        BFPACK(l23, rz, rw);
        int so = r * KCP + c4;
        *(uint2*)(Ah_s + so) = make_uint2(h01, h23);
        *(uint2*)(Al_s + so) = make_uint2(l01, l23);
    }
#pragma unroll
    for (int i = 0; i < 2; i++) {
        int idx = tid + i * 256;
        int r = idx >> 2, c8 = (idx & 3) * 8;
        int so = r * KCP + c8;
        *(uint4*)(Wh_s + so) = whR[i];
        *(uint4*)(Wl_s + so) = wlR[i];
    }
}

__device__ __forceinline__
void tc_gemm_body(__nv_bfloat16* gsm, const float* __restrict__ A,
                  const __nv_bfloat16* __restrict__ Wh,
                  const __nv_bfloat16* __restrict__ Wl,
                  const float* __restrict__ bias, float* __restrict__ C, int vt)
{
    int tid = threadIdx.x;
    int wid = tid >> 5, lane = tid & 31;
    int gid = lane >> 2, tig = lane & 3;
    int wm = wid & 1, wn = wid >> 1;
    int m0 = blockIdx.y * 128, n0 = blockIdx.x * 128;

    float acc[4][4][4];
#pragma unroll
    for (int mi = 0; mi < 4; mi++)
#pragma unroll
        for (int ni = 0; ni < 4; ni++)
#pragma unroll
            for (int j = 0; j < 4; j++) acc[mi][ni][j] = 0.f;

    float4 aR[4]; uint4 whR[2], wlR[2];
    {
        const float* Ar = A + (size_t)m0 * DM;
#pragma unroll
        for (int i = 0; i < 4; i++) {
            int idx = tid + i * 256;
            int r = idx >> 3, c4 = (idx & 7) * 4;
            aR[i] = *(const float4*)(Ar + (size_t)r * DM + c4);
        }
#pragma unroll
        for (int i = 0; i < 2; i++) {
            int idx = tid + i * 256;
            int r = idx >> 2, c8 = (idx & 3) * 8;
            size_t go = (size_t)(n0 + r) * DM + c8;
            whR[i] = *(const uint4*)(Wh + go);
            wlR[i] = *(const uint4*)(Wl + go);
        }
    }
    gemm_store_stage(gsm, tid, aR, whR, wlR);
    __syncthreads();

    for (int kt = 0; kt < 32; kt++) {
        if (kt < 31) {
            int k0n = (kt + 1) * 32;
            const float* Ar = A + (size_t)m0 * DM + k0n;
#pragma unroll
            for (int i = 0; i < 4; i++) {
                int idx = tid + i * 256;
                int r = idx >> 3, c4 = (idx & 7) * 4;
                aR[i] = *(const float4*)(Ar + (size_t)r * DM + c4);
            }
#pragma unroll
            for (int i = 0; i < 2; i++) {
                int idx = tid + i * 256;
                int r = idx >> 2, c8 = (idx & 3) * 8;
                size_t go = (size_t)(n0 + r) * DM + k0n + c8;
                whR[i] = *(const uint4*)(Wh + go);
                wlR[i] = *(const uint4*)(Wl + go);
            }
        }

        __nv_bfloat16* st = gsm + (size_t)(kt & 1) * 4 * GST;
        __nv_bfloat16* Ah_s = st;
        __nv_bfloat16* Al_s = st + GST;
        __nv_bfloat16* Wh_s = st + 2 * GST;
        __nv_bfloat16* Wl_s = st + 3 * GST;

#pragma unroll
        for (int ks = 0; ks < 2; ks++) {
            int kb = ks * 16 + tig * 2;
            u32 bh[4][2], bl[4][2];
#pragma unroll
            for (int ni = 0; ni < 4; ni++) {
                int n = wn * 32 + ni * 8 + gid;
                int off = n * KCP + kb;
                bh[ni][0] = *(const u32*)(Wh_s + off);
                bh[ni][1] = *(const u32*)(Wh_s + off + 8);
                bl[ni][0] = *(const u32*)(Wl_s + off);
                bl[ni][1] = *(const u32*)(Wl_s + off + 8);
            }
#pragma unroll
            for (int mi = 0; mi < 4; mi++) {
                int r = wm * 64 + mi * 16 + gid;
                int off = r * KCP + kb;
                u32 ah0 = *(const u32*)(Ah_s + off);
                u32 ah1 = *(const u32*)(Ah_s + off + 8 * KCP);
                u32 ah2 = *(const u32*)(Ah_s + off + 8);
                u32 ah3 = *(const u32*)(Ah_s + off + 8 * KCP + 8);
                u32 al0 = *(const u32*)(Al_s + off);
                u32 al1 = *(const u32*)(Al_s + off + 8 * KCP);
                u32 al2 = *(const u32*)(Al_s + off + 8);
                u32 al3 = *(const u32*)(Al_s + off + 8 * KCP + 8);
#pragma unroll
                for (int ni = 0; ni < 4; ni++) {
                    HMMA(acc[mi][ni], ah0, ah1, ah2, ah3, bh[ni][0], bh[ni][1]);
                    HMMA(acc[mi][ni], ah0, ah1, ah2, ah3, bl[ni][0], bl[ni][1]);
                    HMMA(acc[mi][ni], al0, al1, al2, al3, bh[ni][0], bh[ni][1]);
                }
            }
        }
        if (kt < 31)
            gemm_store_stage(gsm + (size_t)((kt + 1) & 1) * 4 * GST, tid, aR, whR, wlR);
        __syncthreads();
    }

#pragma unroll
    for (int mi = 0; mi < 4; mi++) {
        int r = m0 + wm * 64 + mi * 16 + gid;
#pragma unroll
        for (int ni = 0; ni < 4; ni++) {
            int c = n0 + wn * 32 + ni * 8 + tig * 2;
            float b0 = bias[c], b1 = bias[c + 1];
            if (!vt) {
                *(float2*)(C + (size_t)r * DM + c) =
                    make_float2(acc[mi][ni][0] + b0, acc[mi][ni][1] + b1);
                *(float2*)(C + (size_t)(r + 8) * DM + c) =
                    make_float2(acc[mi][ni][2] + b0, acc[mi][ni][3] + b1);
            } else {
                int b = r >> 10, s = r & 1023;
                int h = c >> 6, d = c & 63;
                float* base = g_Vt + ((size_t)(b * NH + h) * DKH) * SQ;
                base[(size_t)d * SQ + s]           = acc[mi][ni][0] + b0;
                base[(size_t)(d + 1) * SQ + s]     = acc[mi][ni][1] + b1;
                base[(size_t)d * SQ + s + 8]       = acc[mi][ni][2] + b0;
                base[(size_t)(d + 1) * SQ + s + 8] = acc[mi][ni][3] + b1;
            }
        }
    }
}

__global__ __launch_bounds__(256)
void qkv_gemm_kernel(GemmArgs args) {
    extern __shared__ __nv_bfloat16 gsm[];
    int z = blockIdx.z;
    tc_gemm_body(gsm, args.A[z], g_Wth[z], g_Wtl[z], args.bias[z],
                 z < 2 ? g_P[z] : nullptr, z == 2);
}
__global__ __launch_bounds__(256)
void o_gemm_kernel(const float* __restrict__ bias, float* __restrict__ Cout) {
    extern __shared__ __nv_bfloat16 gsm[];
    tc_gemm_body(gsm, g_O, g_Wth[3], g_Wtl[3], bias, Cout, 0);
}

// ---------------------------------------------------------------------------
// Tensor-core quaternion flash attention, K/V register prefetch, 3 syncs/tile:
// K(t+1)+mask stored in the merge window (all warps past score at sync-a);
// V(t+1) stored after PV (sync-c); visibility covered by next tile's syncs.
// ---------------------------------------------------------------------------
#define STR 72
#define TILE_B (64*STR)

#define S_QH  0
#define S_QL  (S_QH + TILE_B)
#define S_KH  (S_QL + TILE_B)
#define S_KL  (S_KH + TILE_B)
#define S_VH  (S_KL + TILE_B)
#define S_VL  (S_VH + TILE_B)
#define S_PH  (S_VL + TILE_B)           // [4][64][STR]
#define S_PL  (S_PH + 4*TILE_B)
#define S_END (S_PL + 4*TILE_B)
#define ATT_SMEM_BYTES (S_END*2 + 4*64*2*8 + 256)

__device__ __forceinline__
void kv_store_one(__nv_bfloat16* sm, int hioff, int looff, int so, float4 a)
{
    u32 h01, h23, l01, l23;
    BFPACK(h01, a.x, a.y);
    BFPACK(h23, a.z, a.w);
    float rx = a.x - __uint_as_float(h01 << 16);
    float ry = a.y - __uint_as_float(h01 & 0xffff0000u);
    float rz = a.z - __uint_as_float(h23 << 16);
    float rw = a.w - __uint_as_float(h23 & 0xffff0000u);
    BFPACK(l01, rx, ry);
    BFPACK(l23, rz, rw);
    *(uint2*)(sm + hioff + so) = make_uint2(h01, h23);
    *(uint2*)(sm + looff + so) = make_uint2(l01, l23);
}

__global__ __launch_bounds__(256, 1)
void quat_attn_tc_kernel(const int* __restrict__ mask)
{
    extern __shared__ __nv_bfloat16 sm[];
    float2* stats2 = (float2*)(sm + S_END);     // [4][64][2] (max, expsum)
    int*    msk    = (int*)(stats2 + 4 * 64 * 2);

    const int tsrc[4][4] = {{0,1,2,3},{1,0,3,2},{2,3,0,1},{3,2,1,0}};
    const int tsgn[4][4] = {{1,1,1,1},{-1,1,-1,1},{-1,1,1,-1},{-1,-1,1,1}};

    int tid = threadIdx.x;
    int wid = tid >> 5, lane = tid & 31;
    int gid = lane >> 2, tig = lane & 3;
    int mtile = wid >> 1, wh = wid & 1;
    int m16 = mtile * 16;
    int bh = blockIdx.y;
    int b = bh >> 4, h = bh & 15;
    int q0 = blockIdx.x * 64;

    const float* Qg = g_P[0] + (size_t)(b * SQ) * DM + h * DKH;
    const float* Kg = g_P[1] + (size_t)(b * SQ) * DM + h * DKH;
    const float* Vg = g_Vt + (size_t)bh * DKH * SQ;
    const int*   mrow = mask + b * SQ;

    int ldr = tid >> 4, ldc = (tid & 15) * 4;

    // ---- load Q tile (scaled by 1/8) ----
#pragma unroll
    for (int i = 0; i < 4; i++) {
        int r = ldr + i * 16;
        float4 a = *(const float4*)(Qg + (size_t)(q0 + r) * DM + ldc);
        a.x *= 0.125f; a.y *= 0.125f; a.z *= 0.125f; a.w *= 0.125f;
        kv_store_one(sm, S_QH, S_QL, r * STR + ldc, a);
    }
    __syncthreads();

    // ---- persistent Q fragments ----
    u32 qfh[4][4], qfl[4][4];
#pragma unroll
    for (int u = 0; u < 4; u++) {
        int off = (m16 + gid) * STR + u * 16 + tig * 2;
        qfh[u][0] = *(const u32*)(sm + S_QH + off);
        qfh[u][1] = *(const u32*)(sm + S_QH + off + 8 * STR);
        qfh[u][2] = *(const u32*)(sm + S_QH + off + 8);
        qfh[u][3] = *(const u32*)(sm + S_QH + off + 8 * STR + 8);
        qfl[u][0] = *(const u32*)(sm + S_QL + off);
        qfl[u][1] = *(const u32*)(sm + S_QL + off + 8 * STR);
        qfl[u][2] = *(const u32*)(sm + S_QL + off + 8);
        qfl[u][3] = *(const u32*)(sm + S_QL + off + 8 * STR + 8);
    }

    float mrun[4][2], lrun[4][2];
    float U[4][4][4];
#pragma unroll
    for (int c = 0; c < 4; c++) {
#pragma unroll
        for (int j = 0; j < 2; j++) { mrun[c][j] = -1e30f; lrun[c][j] = 0.f; }
#pragma unroll
        for (int nt = 0; nt < 4; nt++)
#pragma unroll
            for (int j = 0; j < 4; j++) U[c][nt][j] = 0.f;
    }

    float4 kR[4], vR[4];
#pragma unroll
    for (int i = 0; i < 4; i++) {
        int r = ldr + i * 16;
        kR[i] = *(const float4*)(Kg + (size_t)r * DM + ldc);
        vR[i] = *(const float4*)(Vg + (size_t)r * SQ + ldc);
    }
#pragma unroll
    for (int i = 0; i < 4; i++) {
        int r = ldr + i * 16;
        kv_store_one(sm, S_KH, S_KL, r * STR + ldc, kR[i]);
        kv_store_one(sm, S_VH, S_VL, r * STR + ldc, vR[i]);
    }
    if (tid < 64) msk[tid] = mrow[tid];
    __syncthreads();

    for (int t = 0; t < 16; t++) {
        int n0 = t * 64;
        // prefetch next tile K/V into registers
        if (t < 15) {
            int n1 = n0 + 64;
#pragma unroll
            for (int i = 0; i < 4; i++) {
                int r = ldr + i * 16;
                kR[i] = *(const float4*)(Kg + (size_t)(n1 + r) * DM + ldc);
                vR[i] = *(const float4*)(Vg + (size_t)r * SQ + n1 + ldc);
            }
        }

        // ---- score MMAs (read K smem) ----
        float sc[4][4][4];
#pragma unroll
        for (int c = 0; c < 4; c++)
#pragma unroll
            for (int nt = 0; nt < 4; nt++)
#pragma unroll
                for (int j = 0; j < 4; j++) sc[c][nt][j] = 0.f;

#pragma unroll
        for (int nt = 0; nt < 4; nt++) {
            int kb0 = wh * 32 + nt * 8;
            u32 kf[4][2][2];
#pragma unroll
            for (int comp = 0; comp < 4; comp++) {
                int off = (kb0 + gid) * STR + comp * 16 + tig * 2;
                kf[comp][0][0] = *(const u32*)(sm + S_KH + off);
                kf[comp][0][1] = *(const u32*)(sm + S_KH + off + 8);
                kf[comp][1][0] = *(const u32*)(sm + S_KL + off);
                kf[comp][1][1] = *(const u32*)(sm + S_KL + off + 8);
            }
#pragma unroll
            for (int c = 0; c < 4; c++)
#pragma unroll
                for (int u = 0; u < 4; u++) {
                    int src = tsrc[u][c];
                    u32 bh0 = kf[src][0][0], bh1 = kf[src][0][1];
                    u32 bl0 = kf[src][1][0], bl1 = kf[src][1][1];
                    if (tsgn[u][c] < 0) {
                        bh0 ^= SGNM; bh1 ^= SGNM; bl0 ^= SGNM; bl1 ^= SGNM;
                    }
                    HMMA(sc[c][nt], qfh[u][0], qfh[u][1], qfh[u][2], qfh[u][3], bh0, bh1);
                    HMMA(sc[c][nt], qfh[u][0], qfh[u][1], qfh[u][2], qfh[u][3], bl0, bl1);
                    HMMA(sc[c][nt], qfl[u][0], qfl[u][1], qfl[u][2], qfl[u][3], bh0, bh1);
                }
        }

        // ---- mask (reads msk; last use before sync-a) ----
#pragma unroll
        for (int nt = 0; nt < 4; nt++) {
            int kb0 = wh * 32 + nt * 8 + tig * 2;
            int m0v = msk[kb0], m1v = msk[kb0 + 1];
#pragma unroll
            for (int c = 0; c < 4; c++) {
                if (!m0v) { sc[c][nt][0] = -1e9f; sc[c][nt][2] = -1e9f; }
                if (!m1v) { sc[c][nt][1] = -1e9f; sc[c][nt][3] = -1e9f; }
            }
        }

        // ---- per-warp tile softmax, single exchange ----
        float tmx[4][2], tsum[4][2];
#pragma unroll
        for (int c = 0; c < 4; c++) {
            float t0 = -1e30f, t1 = -1e30f;
#pragma unroll
            for (int nt = 0; nt < 4; nt++) {
                t0 = fmaxf(t0, fmaxf(sc[c][nt][0], sc[c][nt][1]));
                t1 = fmaxf(t1, fmaxf(sc[c][nt][2], sc[c][nt][3]));
            }
            t0 = fmaxf(t0, __shfl_xor_sync(0xffffffffu, t0, 1));
            t0 = fmaxf(t0, __shfl_xor_sync(0xffffffffu, t0, 2));
            t1 = fmaxf(t1, __shfl_xor_sync(0xffffffffu, t1, 1));
            t1 = fmaxf(t1, __shfl_xor_sync(0xffffffffu, t1, 2));
            float s0 = 0.f, s1 = 0.f;
#pragma unroll
            for (int nt = 0; nt < 4; nt++) {
                sc[c][nt][0] = __expf(sc[c][nt][0] - t0);
                sc[c][nt][1] = __expf(sc[c][nt][1] - t0);
                sc[c][nt][2] = __expf(sc[c][nt][2] - t1);
                sc[c][nt][3] = __expf(sc[c][nt][3] - t1);
                s0 += sc[c][nt][0] + sc[c][nt][1];
                s1 += sc[c][nt][2] + sc[c][nt][3];
            }
            s0 += __shfl_xor_sync(0xffffffffu, s0, 1);
            s0 += __shfl_xor_sync(0xffffffffu, s0, 2);
            s1 += __shfl_xor_sync(0xffffffffu, s1, 1);
            s1 += __shfl_xor_sync(0xffffffffu, s1, 2);
            tmx[c][0] = t0; tmx[c][1] = t1;
            tsum[c][0] = s0; tsum[c][1] = s1;
            if (tig == 0) {
                stats2[(c * 64 + m16 + gid) * 2 + wh] = make_float2(t0, s0);
                stats2[(c * 64 + m16 + gid + 8) * 2 + wh] = make_float2(t1, s1);
            }
        }
        __syncthreads();   // (a) stats visible; all warps past score + mask

        // ---- store K(t+1)+mask into smem (K reads are done block-wide) ----
        if (t < 15) {
#pragma unroll
            for (int i = 0; i < 4; i++) {
                int r = ldr + i * 16;
                kv_store_one(sm, S_KH, S_KL, r * STR + ldc, kR[i]);
            }
            if (tid < 64) msk[tid] = mrow[n0 + 64 + tid];
        }

        // ---- merge with partner half, rescale U, pack scaled P ----
#pragma unroll
        for (int c = 0; c < 4; c++) {
            float2 o0 = stats2[(c * 64 + m16 + gid) * 2 + (wh ^ 1)];
            float2 o1 = stats2[(c * 64 + m16 + gid + 8) * 2 + (wh ^ 1)];
            float mn0 = fmaxf(mrun[c][0], fmaxf(tmx[c][0], o0.x));
            float mn1 = fmaxf(mrun[c][1], fmaxf(tmx[c][1], o1.x));
            float corr0 = __expf(mrun[c][0] - mn0);
            float corr1 = __expf(mrun[c][1] - mn1);
            float f0 = __expf(tmx[c][0] - mn0);
            float f1 = __expf(tmx[c][1] - mn1);
            float g0 = __expf(o0.x - mn0);
            float g1 = __expf(o1.x - mn1);
            lrun[c][0] = lrun[c][0] * corr0 + tsum[c][0] * f0 + o0.y * g0;
            lrun[c][1] = lrun[c][1] * corr1 + tsum[c][1] * f1 + o1.y * g1;
            mrun[c][0] = mn0; mrun[c][1] = mn1;
#pragma unroll
            for (int nt = 0; nt < 4; nt++) {
                U[c][nt][0] *= corr0;
                U[c][nt][1] *= corr0;
                U[c][nt][2] *= corr1;
                U[c][nt][3] *= corr1;
            }
#pragma unroll
            for (int nt = 0; nt < 4; nt++) {
                int key = wh * 32 + nt * 8 + tig * 2;
                float p0 = sc[c][nt][0] * f0, p1 = sc[c][nt][1] * f0;
                u32 h01, l01;
                BFPACK(h01, p0, p1);
                float rx = p0 - __uint_as_float(h01 << 16);
                float ry = p1 - __uint_as_float(h01 & 0xffff0000u);
                BFPACK(l01, rx, ry);
                int ro = (c * 64 + m16 + gid) * STR + key;
                *(u32*)(sm + S_PH + ro) = h01;
                *(u32*)(sm + S_PL + ro) = l01;
                float p2 = sc[c][nt][2] * f1, p3 = sc[c][nt][3] * f1;
                BFPACK(h01, p2, p3);
                rx = p2 - __uint_as_float(h01 << 16);
                ry = p3 - __uint_as_float(h01 & 0xffff0000u);
                BFPACK(l01, rx, ry);
                ro = (c * 64 + m16 + gid + 8) * STR + key;
                *(u32*)(sm + S_PH + ro) = h01;
                *(u32*)(sm + S_PL + ro) = l01;
            }
        }
        __syncthreads();   // (b) P + K(t+1) + mask visible

        // ---- PV MMAs (read P, V) ----
#pragma unroll
        for (int c = 0; c < 4; c++) {
#pragma unroll
            for (int u = 0; u < 4; u++) {
                int ao = (c * 64 + m16 + gid) * STR + u * 16 + tig * 2;
                u32 pa0 = *(const u32*)(sm + S_PH + ao);
                u32 pa1 = *(const u32*)(sm + S_PH + ao + 8 * STR);
                u32 pa2 = *(const u32*)(sm + S_PH + ao + 8);
                u32 pa3 = *(const u32*)(sm + S_PH + ao + 8 * STR + 8);
                u32 la0 = *(const u32*)(sm + S_PL + ao);
                u32 la1 = *(const u32*)(sm + S_PL + ao + 8 * STR);
                u32 la2 = *(const u32*)(sm + S_PL + ao + 8);
                u32 la3 = *(const u32*)(sm + S_PL + ao + 8 * STR + 8);
#pragma unroll
                for (int nt = 0; nt < 4; nt++) {
                    int oc = wh * 2 + (nt >> 1);
                    int src = tsrc[c][oc];
                    u32 smask = (tsgn[c][oc] < 0) ? SGNM : 0u;
                    int bo = (src * 16 + (nt & 1) * 8 + gid) * STR + u * 16 + tig * 2;
                    u32 vh0 = *(const u32*)(sm + S_VH + bo) ^ smask;
                    u32 vh1 = *(const u32*)(sm + S_VH + bo + 8) ^ smask;
                    u32 vl0 = *(const u32*)(sm + S_VL + bo) ^ smask;
                    u32 vl1 = *(const u32*)(sm + S_VL + bo + 8) ^ smask;
                    HMMA(U[c][nt], pa0, pa1, pa2, pa3, vh0, vh1);
                    HMMA(U[c][nt], pa0, pa1, pa2, pa3, vl0, vl1);
                    HMMA(U[c][nt], la0, la1, la2, la3, vh0, vh1);
                }
            }
        }
        __syncthreads();   // (c) PV reads done before V overwrite

        // ---- store V(t+1); visibility ensured by next tile's syncs ----
        if (t < 15) {
#pragma unroll
            for (int i = 0; i < 4; i++) {
                int r = ldr + i * 16;
                kv_store_one(sm, S_VH, S_VL, r * STR + ldc, vR[i]);
            }
        }
        // P rewritten only after next tile's sync (a); V read only after next
        // tile's sync (b) -> no extra sync needed here.
    }

    // ---- register epilogue ----
    float inv[4][2];
#pragma unroll
    for (int c = 0; c < 4; c++) {
        inv[c][0] = 1.f / lrun[c][0];
        inv[c][1] = 1.f / lrun[c][1];
    }
    float* Og = g_O + (size_t)(b * SQ) * DM + h * DKH;
    int r0 = q0 + m16 + gid;
#pragma unroll
    for (int nt = 0; nt < 4; nt++) {
        int col = wh * 32 + nt * 8 + tig * 2;
        float o0 = 0.f, o1 = 0.f, o2 = 0.f, o3 = 0.f;
#pragma unroll
        for (int c = 0; c < 4; c++) {
            o0 += U[c][nt][0] * inv[c][0];
            o1 += U[c][nt][1] * inv[c][0];
            o2 += U[c][nt][2] * inv[c][1];
            o3 += U[c][nt][3] * inv[c][1];
        }
        *(float2*)(Og + (size_t)r0 * DM + col) = make_float2(o0, o1);
        *(float2*)(Og + (size_t)(r0 + 8) * DM + col) = make_float2(o2, o3);
    }
}

// ---------------------------------------------------------------------------
extern "C" void kernel_launch(void* const* d_in, const int* in_sizes, int n_in,
                              void* d_out, int out_size)
{
    (void)in_sizes; (void)n_in; (void)out_size;
    // 0 q, 1 k, 2 v, 3 mask, 4-19 weights, 20 bq, 21 bk, 22 bv, 23 bo
    WPtrs wp;
    for (int i = 0; i < 16; i++) wp.w[i] = (const float*)d_in[4 + i];

    build_wbig_kernel<<<dim3(32, 32, 4), 256>>>(wp);

    GemmArgs ga;
    for (int z = 0; z < 3; z++) {
        ga.A[z]    = (const float*)d_in[z];
        ga.bias[z] = (const float*)d_in[20 + z];
    }
    cudaFuncSetAttribute(qkv_gemm_kernel,
                         cudaFuncAttributeMaxDynamicSharedMemorySize, GEMM_SMEM_BYTES);
    cudaFuncSetAttribute(o_gemm_kernel,
                         cudaFuncAttributeMaxDynamicSharedMemorySize, GEMM_SMEM_BYTES);

    dim3 qkvgrid(DM / 128, MROWS / 128, 3);   // (8, 16, 3)
    qkv_gemm_kernel<<<qkvgrid, 256, GEMM_SMEM_BYTES>>>(ga);

    cudaFuncSetAttribute(quat_attn_tc_kernel,
                         cudaFuncAttributeMaxDynamicSharedMemorySize, ATT_SMEM_BYTES);
    quat_attn_tc_kernel<<<dim3(SQ / 64, BSZ * NH), 256, ATT_SMEM_BYTES>>>(
        (const int*)d_in[3]);

    dim3 ogrid(DM / 128, MROWS / 128);        // (8, 16)
    o_gemm_kernel<<<ogrid, 256, GEMM_SMEM_BYTES>>>((const float*)d_in[23], (float*)d_out);
}

// round 16
// speedup vs baseline: 1.0324x; 1.0039x over previous
#include <cuda_runtime.h>
#include <cuda_bf16.h>
#include <cstdint>
#include <math.h>

#define SQ   1024
#define DM   1024
#define NH   16
#define DKH  64
#define BSZ  2
#define MROWS (BSZ*SQ)

typedef uint32_t u32;

// ---------------------------------------------------------------------------
// Device scratch
// ---------------------------------------------------------------------------
__device__ __nv_bfloat16 g_Wth[4][DM*DM];  // W^T hi (K-major [n][k])
__device__ __nv_bfloat16 g_Wtl[4][DM*DM];  // W^T lo
__device__ float g_P[2][MROWS*DM];         // projected Q,K
__device__ float g_Vt[BSZ*NH*DKH*SQ];      // projected V, transposed [b,h,d,S]
__device__ float g_O[MROWS*DM];            // attention output

__constant__ int   c_SRC[16] = {0,1,2,3,  1,0,3,2,  2,3,0,1,  3,2,1,0};
__constant__ float c_SGN[16] = {1.f,1.f,1.f,1.f,  -1.f,1.f,-1.f,1.f,
                                -1.f,1.f,1.f,-1.f, -1.f,-1.f,1.f,1.f};

struct WPtrs { const float* w[16]; };
struct GemmArgs { const float* A[3]; const float* bias[3]; };

#define BFPACK(r, flo, fhi) \
    asm("cvt.rn.bf16x2.f32 %0, %1, %2;" : "=r"(r) : "f"(fhi), "f"(flo))

#define HMMA(c, a0, a1, a2, a3, b0, b1) \
    asm volatile("mma.sync.aligned.m16n8k16.row.col.f32.bf16.bf16.f32 " \
        "{%0,%1,%2,%3}, {%4,%5,%6,%7}, {%8,%9}, {%0,%1,%2,%3};" \
        : "+f"((c)[0]), "+f"((c)[1]), "+f"((c)[2]), "+f"((c)[3]) \
        : "r"(a0), "r"(a1), "r"(a2), "r"(a3), "r"(b0), "r"(b1))

#define SGNM 0x80008000u

// ---------------------------------------------------------------------------
__global__ __launch_bounds__(256)
void build_wbig_kernel(WPtrs p) {
    __shared__ float s[32][33];
    int tx = threadIdx.x & 31, ty = threadIdx.x >> 5;
    int k0 = blockIdx.x * 32, n0 = blockIdx.y * 32, which = blockIdx.z;
    int rb = k0 >> 8, cb = n0 >> 8;
    float sgn = c_SGN[rb * 4 + cb];
    const float* src = p.w[which * 4 + c_SRC[rb * 4 + cb]];
#pragma unroll
    for (int i = 0; i < 4; i++) {
        int kl = ty + i * 8;
        s[kl][tx] = sgn * src[((k0 + kl) & 255) * 256 + ((n0 + tx) & 255)];
    }
    __syncthreads();
#pragma unroll
    for (int i = 0; i < 4; i++) {
        int nl = ty + i * 8;
        float v = s[tx][nl];
        __nv_bfloat16 hi = __float2bfloat16_rn(v);
        __nv_bfloat16 lo = __float2bfloat16_rn(v - __bfloat162float(hi));
        size_t o = (size_t)(n0 + nl) * DM + k0 + tx;
        g_Wth[which][o] = hi;
        g_Wtl[which][o] = lo;
    }
}

// ---------------------------------------------------------------------------
// Tensor-core GEMM, double-buffered, term-major MMA order (RAW-chain free).
// ---------------------------------------------------------------------------
#define KCP 40
#define GST (128 * KCP)
#define GEMM_SMEM_BYTES (2 * 4 * GST * 2)  // 81920 B

__device__ __forceinline__
void gemm_store_stage(__nv_bfloat16* base, int tid,
                      const float4 aR[4], const uint4 whR[2], const uint4 wlR[2])
{
    __nv_bfloat16* Ah_s = base;
    __nv_bfloat16* Al_s = base + GST;
    __nv_bfloat16* Wh_s = base + 2 * GST;
    __nv_bfloat16* Wl_s = base + 3 * GST;
#pragma unroll
    for (int i = 0; i < 4; i++) {
        int idx = tid + i * 256;
        int r = idx >> 3, c4 = (idx & 7) * 4;
        float4 a = aR[i];
        u32 h01, h23, l01, l23;
        BFPACK(h01, a.x, a.y);
        BFPACK(h23, a.z, a.w);
        float rx = a.x - __uint_as_float(h01 << 16);
        float ry = a.y - __uint_as_float(h01 & 0xffff0000u);
        float rz = a.z - __uint_as_float(h23 << 16);
        float rw = a.w - __uint_as_float(h23 & 0xffff0000u);
        BFPACK(l01, rx, ry);
        BFPACK(l23, rz, rw);
        int so = r * KCP + c4;
        *(uint2*)(Ah_s + so) = make_uint2(h01, h23);
        *(uint2*)(Al_s + so) = make_uint2(l01, l23);
    }
#pragma unroll
    for (int i = 0; i < 2; i++) {
        int idx = tid + i * 256;
        int r = idx >> 2, c8 = (idx & 3) * 8;
        int so = r * KCP + c8;
        *(uint4*)(Wh_s + so) = whR[i];
        *(uint4*)(Wl_s + so) = wlR[i];
    }
}

__device__ __forceinline__
void tc_gemm_body(__nv_bfloat16* gsm, const float* __restrict__ A,
                  const __nv_bfloat16* __restrict__ Wh,
                  const __nv_bfloat16* __restrict__ Wl,
                  const float* __restrict__ bias, float* __restrict__ C, int vt)
{
    int tid = threadIdx.x;
    int wid = tid >> 5, lane = tid & 31;
    int gid = lane >> 2, tig = lane & 3;
    int wm = wid & 1, wn = wid >> 1;
    int m0 = blockIdx.y * 128, n0 = blockIdx.x * 128;

    float acc[4][4][4];
#pragma unroll
    for (int mi = 0; mi < 4; mi++)
#pragma unroll
        for (int ni = 0; ni < 4; ni++)
#pragma unroll
            for (int j = 0; j < 4; j++) acc[mi][ni][j] = 0.f;

    float4 aR[4]; uint4 whR[2], wlR[2];
    {
        const float* Ar = A + (size_t)m0 * DM;
#pragma unroll
        for (int i = 0; i < 4; i++) {
            int idx = tid + i * 256;
            int r = idx >> 3, c4 = (idx & 7) * 4;
            aR[i] = *(const float4*)(Ar + (size_t)r * DM + c4);
        }
#pragma unroll
        for (int i = 0; i < 2; i++) {
            int idx = tid + i * 256;
            int r = idx >> 2, c8 = (idx & 3) * 8;
            size_t go = (size_t)(n0 + r) * DM + c8;
            whR[i] = *(const uint4*)(Wh + go);
            wlR[i] = *(const uint4*)(Wl + go);
        }
    }
    gemm_store_stage(gsm, tid, aR, whR, wlR);
    __syncthreads();

    for (int kt = 0; kt < 32; kt++) {
        if (kt < 31) {
            int k0n = (kt + 1) * 32;
            const float* Ar = A + (size_t)m0 * DM + k0n;
#pragma unroll
            for (int i = 0; i < 4; i++) {
                int idx = tid + i * 256;
                int r = idx >> 3, c4 = (idx & 7) * 4;
                aR[i] = *(const float4*)(Ar + (size_t)r * DM + c4);
            }
#pragma unroll
            for (int i = 0; i < 2; i++) {
                int idx = tid + i * 256;
                int r = idx >> 2, c8 = (idx & 3) * 8;
                size_t go = (size_t)(n0 + r) * DM + k0n + c8;
                whR[i] = *(const uint4*)(Wh + go);
                wlR[i] = *(const uint4*)(Wl + go);
            }
        }

        __nv_bfloat16* st = gsm + (size_t)(kt & 1) * 4 * GST;
        __nv_bfloat16* Ah_s = st;
        __nv_bfloat16* Al_s = st + GST;
        __nv_bfloat16* Wh_s = st + 2 * GST;
        __nv_bfloat16* Wl_s = st + 3 * GST;

#pragma unroll
        for (int ks = 0; ks < 2; ks++) {
            int kb = ks * 16 + tig * 2;
            u32 bh[4][2], bl[4][2];
#pragma unroll
            for (int ni = 0; ni < 4; ni++) {
                int n = wn * 32 + ni * 8 + gid;
                int off = n * KCP + kb;
                bh[ni][0] = *(const u32*)(Wh_s + off);
                bh[ni][1] = *(const u32*)(Wh_s + off + 8);
                bl[ni][0] = *(const u32*)(Wl_s + off);
                bl[ni][1] = *(const u32*)(Wl_s + off + 8);
            }
            u32 ah[4][4], al[4][4];
#pragma unroll
            for (int mi = 0; mi < 4; mi++) {
                int r = wm * 64 + mi * 16 + gid;
                int off = r * KCP + kb;
                ah[mi][0] = *(const u32*)(Ah_s + off);
                ah[mi][1] = *(const u32*)(Ah_s + off + 8 * KCP);
                ah[mi][2] = *(const u32*)(Ah_s + off + 8);
                ah[mi][3] = *(const u32*)(Ah_s + off + 8 * KCP + 8);
                al[mi][0] = *(const u32*)(Al_s + off);
                al[mi][1] = *(const u32*)(Al_s + off + 8 * KCP);
                al[mi][2] = *(const u32*)(Al_s + off + 8);
                al[mi][3] = *(const u32*)(Al_s + off + 8 * KCP + 8);
            }
            // term-major passes: accumulator reuse distance = 16 MMAs
#pragma unroll
            for (int mi = 0; mi < 4; mi++)
#pragma unroll
                for (int ni = 0; ni < 4; ni++)
                    HMMA(acc[mi][ni], ah[mi][0], ah[mi][1], ah[mi][2], ah[mi][3],
                         bh[ni][0], bh[ni][1]);
#pragma unroll
            for (int mi = 0; mi < 4; mi++)
#pragma unroll
                for (int ni = 0; ni < 4; ni++)
                    HMMA(acc[mi][ni], ah[mi][0], ah[mi][1], ah[mi][2], ah[mi][3],
                         bl[ni][0], bl[ni][1]);
#pragma unroll
            for (int mi = 0; mi < 4; mi++)
#pragma unroll
                for (int ni = 0; ni < 4; ni++)
                    HMMA(acc[mi][ni], al[mi][0], al[mi][1], al[mi][2], al[mi][3],
                         bh[ni][0], bh[ni][1]);
        }
        if (kt < 31)
            gemm_store_stage(gsm + (size_t)((kt + 1) & 1) * 4 * GST, tid, aR, whR, wlR);
        __syncthreads();
    }

#pragma unroll
    for (int mi = 0; mi < 4; mi++) {
        int r = m0 + wm * 64 + mi * 16 + gid;
#pragma unroll
        for (int ni = 0; ni < 4; ni++) {
            int c = n0 + wn * 32 + ni * 8 + tig * 2;
            float b0 = bias[c], b1 = bias[c + 1];
            if (!vt) {
                *(float2*)(C + (size_t)r * DM + c) =
                    make_float2(acc[mi][ni][0] + b0, acc[mi][ni][1] + b1);
                *(float2*)(C + (size_t)(r + 8) * DM + c) =
                    make_float2(acc[mi][ni][2] + b0, acc[mi][ni][3] + b1);
            } else {
                int b = r >> 10, s = r & 1023;
                int h = c >> 6, d = c & 63;
                float* base = g_Vt + ((size_t)(b * NH + h) * DKH) * SQ;
                base[(size_t)d * SQ + s]           = acc[mi][ni][0] + b0;
                base[(size_t)(d + 1) * SQ + s]     = acc[mi][ni][1] + b1;
                base[(size_t)d * SQ + s + 8]       = acc[mi][ni][2] + b0;
                base[(size_t)(d + 1) * SQ + s + 8] = acc[mi][ni][3] + b1;
            }
        }
    }
}

__global__ __launch_bounds__(256)
void qkv_gemm_kernel(GemmArgs args) {
    extern __shared__ __nv_bfloat16 gsm[];
    int z = blockIdx.z;
    tc_gemm_body(gsm, args.A[z], g_Wth[z], g_Wtl[z], args.bias[z],
                 z < 2 ? g_P[z] : nullptr, z == 2);
}
__global__ __launch_bounds__(256)
void o_gemm_kernel(const float* __restrict__ bias, float* __restrict__ Cout) {
    extern __shared__ __nv_bfloat16 gsm[];
    tc_gemm_body(gsm, g_O, g_Wth[3], g_Wtl[3], bias, Cout, 0);
}

// ---------------------------------------------------------------------------
// Tensor-core quaternion flash attention, 3 syncs/tile, term-major MMA order.
// ---------------------------------------------------------------------------
#define STR 72
#define TILE_B (64*STR)

#define S_QH  0
#define S_QL  (S_QH + TILE_B)
#define S_KH  (S_QL + TILE_B)
#define S_KL  (S_KH + TILE_B)
#define S_VH  (S_KL + TILE_B)
#define S_VL  (S_VH + TILE_B)
#define S_PH  (S_VL + TILE_B)           // [4][64][STR]
#define S_PL  (S_PH + 4*TILE_B)
#define S_END (S_PL + 4*TILE_B)
#define ATT_SMEM_BYTES (S_END*2 + 4*64*2*8 + 256)

__device__ __forceinline__
void kv_store_one(__nv_bfloat16* sm, int hioff, int looff, int so, float4 a)
{
    u32 h01, h23, l01, l23;
    BFPACK(h01, a.x, a.y);
    BFPACK(h23, a.z, a.w);
    float rx = a.x - __uint_as_float(h01 << 16);
    float ry = a.y - __uint_as_float(h01 & 0xffff0000u);
    float rz = a.z - __uint_as_float(h23 << 16);
    float rw = a.w - __uint_as_float(h23 & 0xffff0000u);
    BFPACK(l01, rx, ry);
    BFPACK(l23, rz, rw);
    *(uint2*)(sm + hioff + so) = make_uint2(h01, h23);
    *(uint2*)(sm + looff + so) = make_uint2(l01, l23);
}

__global__ __launch_bounds__(256, 1)
void quat_attn_tc_kernel(const int* __restrict__ mask)
{
    extern __shared__ __nv_bfloat16 sm[];
    float2* stats2 = (float2*)(sm + S_END);     // [4][64][2] (max, expsum)
    int*    msk    = (int*)(stats2 + 4 * 64 * 2);

    const int tsrc[4][4] = {{0,1,2,3},{1,0,3,2},{2,3,0,1},{3,2,1,0}};
    const int tsgn[4][4] = {{1,1,1,1},{-1,1,-1,1},{-1,1,1,-1},{-1,-1,1,1}};

    int tid = threadIdx.x;
    int wid = tid >> 5, lane = tid & 31;
    int gid = lane >> 2, tig = lane & 3;
    int mtile = wid >> 1, wh = wid & 1;
    int m16 = mtile * 16;
    int bh = blockIdx.y;
    int b = bh >> 4, h = bh & 15;
    int q0 = blockIdx.x * 64;

    const float* Qg = g_P[0] + (size_t)(b * SQ) * DM + h * DKH;
    const float* Kg = g_P[1] + (size_t)(b * SQ) * DM + h * DKH;
    const float* Vg = g_Vt + (size_t)bh * DKH * SQ;
    const int*   mrow = mask + b * SQ;

    int ldr = tid >> 4, ldc = (tid & 15) * 4;

    // ---- load Q tile (scaled by 1/8) ----
#pragma unroll
    for (int i = 0; i < 4; i++) {
        int r = ldr + i * 16;
        float4 a = *(const float4*)(Qg + (size_t)(q0 + r) * DM + ldc);
        a.x *= 0.125f; a.y *= 0.125f; a.z *= 0.125f; a.w *= 0.125f;
        kv_store_one(sm, S_QH, S_QL, r * STR + ldc, a);
    }
    __syncthreads();

    // ---- persistent Q fragments ----
    u32 qfh[4][4], qfl[4][4];
#pragma unroll
    for (int u = 0; u < 4; u++) {
        int off = (m16 + gid) * STR + u * 16 + tig * 2;
        qfh[u][0] = *(const u32*)(sm + S_QH + off);
        qfh[u][1] = *(const u32*)(sm + S_QH + off + 8 * STR);
        qfh[u][2] = *(const u32*)(sm + S_QH + off + 8);
        qfh[u][3] = *(const u32*)(sm + S_QH + off + 8 * STR + 8);
        qfl[u][0] = *(const u32*)(sm + S_QL + off);
        qfl[u][1] = *(const u32*)(sm + S_QL + off + 8 * STR);
        qfl[u][2] = *(const u32*)(sm + S_QL + off + 8);
        qfl[u][3] = *(const u32*)(sm + S_QL + off + 8 * STR + 8);
    }

    float mrun[4][2], lrun[4][2];
    float U[4][4][4];
#pragma unroll
    for (int c = 0; c < 4; c++) {
#pragma unroll
        for (int j = 0; j < 2; j++) { mrun[c][j] = -1e30f; lrun[c][j] = 0.f; }
#pragma unroll
        for (int nt = 0; nt < 4; nt++)
#pragma unroll
            for (int j = 0; j < 4; j++) U[c][nt][j] = 0.f;
    }

    float4 kR[4], vR[4];
#pragma unroll
    for (int i = 0; i < 4; i++) {
        int r = ldr + i * 16;
        kR[i] = *(const float4*)(Kg + (size_t)r * DM + ldc);
        vR[i] = *(const float4*)(Vg + (size_t)r * SQ + ldc);
    }
#pragma unroll
    for (int i = 0; i < 4; i++) {
        int r = ldr + i * 16;
        kv_store_one(sm, S_KH, S_KL, r * STR + ldc, kR[i]);
        kv_store_one(sm, S_VH, S_VL, r * STR + ldc, vR[i]);
    }
    if (tid < 64) msk[tid] = mrow[tid];
    __syncthreads();

    for (int t = 0; t < 16; t++) {
        int n0 = t * 64;
        if (t < 15) {
            int n1 = n0 + 64;
#pragma unroll
            for (int i = 0; i < 4; i++) {
                int r = ldr + i * 16;
                kR[i] = *(const float4*)(Kg + (size_t)(n1 + r) * DM + ldc);
                vR[i] = *(const float4*)(Vg + (size_t)r * SQ + n1 + ldc);
            }
        }

        // ---- score MMAs, term-major (sc[c][nt] reuse distance 4) ----
        float sc[4][4][4];
#pragma unroll
        for (int c = 0; c < 4; c++)
#pragma unroll
            for (int nt = 0; nt < 4; nt++)
#pragma unroll
                for (int j = 0; j < 4; j++) sc[c][nt][j] = 0.f;

#pragma unroll
        for (int nt = 0; nt < 4; nt++) {
            int kb0 = wh * 32 + nt * 8;
            u32 kf[4][2][2];
#pragma unroll
            for (int comp = 0; comp < 4; comp++) {
                int off = (kb0 + gid) * STR + comp * 16 + tig * 2;
                kf[comp][0][0] = *(const u32*)(sm + S_KH + off);
                kf[comp][0][1] = *(const u32*)(sm + S_KH + off + 8);
                kf[comp][1][0] = *(const u32*)(sm + S_KL + off);
                kf[comp][1][1] = *(const u32*)(sm + S_KL + off + 8);
            }
            // pass 1: Qh x Kh
#pragma unroll
            for (int u = 0; u < 4; u++)
#pragma unroll
                for (int c = 0; c < 4; c++) {
                    int src = tsrc[u][c];
                    u32 s = (tsgn[u][c] < 0) ? SGNM : 0u;
                    HMMA(sc[c][nt], qfh[u][0], qfh[u][1], qfh[u][2], qfh[u][3],
                         kf[src][0][0] ^ s, kf[src][0][1] ^ s);
                }
            // pass 2: Qh x Kl
#pragma unroll
            for (int u = 0; u < 4; u++)
#pragma unroll
                for (int c = 0; c < 4; c++) {
                    int src = tsrc[u][c];
                    u32 s = (tsgn[u][c] < 0) ? SGNM : 0u;
                    HMMA(sc[c][nt], qfh[u][0], qfh[u][1], qfh[u][2], qfh[u][3],
                         kf[src][1][0] ^ s, kf[src][1][1] ^ s);
                }
            // pass 3: Ql x Kh
#pragma unroll
            for (int u = 0; u < 4; u++)
#pragma unroll
                for (int c = 0; c < 4; c++) {
                    int src = tsrc[u][c];
                    u32 s = (tsgn[u][c] < 0) ? SGNM : 0u;
                    HMMA(sc[c][nt], qfl[u][0], qfl[u][1], qfl[u][2], qfl[u][3],
                         kf[src][0][0] ^ s, kf[src][0][1] ^ s);
                }
        }

        // ---- mask ----
#pragma unroll
        for (int nt = 0; nt < 4; nt++) {
            int kb0 = wh * 32 + nt * 8 + tig * 2;
            int m0v = msk[kb0], m1v = msk[kb0 + 1];
#pragma unroll
            for (int c = 0; c < 4; c++) {
                if (!m0v) { sc[c][nt][0] = -1e9f; sc[c][nt][2] = -1e9f; }
                if (!m1v) { sc[c][nt][1] = -1e9f; sc[c][nt][3] = -1e9f; }
            }
        }

        // ---- per-warp tile softmax, single exchange ----
        float tmx[4][2], tsum[4][2];
#pragma unroll
        for (int c = 0; c < 4; c++) {
            float t0 = -1e30f, t1 = -1e30f;
#pragma unroll
            for (int nt = 0; nt < 4; nt++) {
                t0 = fmaxf(t0, fmaxf(sc[c][nt][0], sc[c][nt][1]));
                t1 = fmaxf(t1, fmaxf(sc[c][nt][2], sc[c][nt][3]));
            }
            t0 = fmaxf(t0, __shfl_xor_sync(0xffffffffu, t0, 1));
            t0 = fmaxf(t0, __shfl_xor_sync(0xffffffffu, t0, 2));
            t1 = fmaxf(t1, __shfl_xor_sync(0xffffffffu, t1, 1));
            t1 = fmaxf(t1, __shfl_xor_sync(0xffffffffu, t1, 2));
            float s0 = 0.f, s1 = 0.f;
#pragma unroll
            for (int nt = 0; nt < 4; nt++) {
                sc[c][nt][0] = __expf(sc[c][nt][0] - t0);
                sc[c][nt][1] = __expf(sc[c][nt][1] - t0);
                sc[c][nt][2] = __expf(sc[c][nt][2] - t1);
                sc[c][nt][3] = __expf(sc[c][nt][3] - t1);
                s0 += sc[c][nt][0] + sc[c][nt][1];
                s1 += sc[c][nt][2] + sc[c][nt][3];
            }
            s0 += __shfl_xor_sync(0xffffffffu, s0, 1);
            s0 += __shfl_xor_sync(0xffffffffu, s0, 2);
            s1 += __shfl_xor_sync(0xffffffffu, s1, 1);
            s1 += __shfl_xor_sync(0xffffffffu, s1, 2);
            tmx[c][0] = t0; tmx[c][1] = t1;
            tsum[c][0] = s0; tsum[c][1] = s1;
            if (tig == 0) {
                stats2[(c * 64 + m16 + gid) * 2 + wh] = make_float2(t0, s0);
                stats2[(c * 64 + m16 + gid + 8) * 2 + wh] = make_float2(t1, s1);
            }
        }
        __syncthreads();   // (a) stats visible; all warps past score + mask

        // ---- store K(t+1)+mask into smem ----
        if (t < 15) {
#pragma unroll
            for (int i = 0; i < 4; i++) {
                int r = ldr + i * 16;
                kv_store_one(sm, S_KH, S_KL, r * STR + ldc, kR[i]);
            }
            if (tid < 64) msk[tid] = mrow[n0 + 64 + tid];
        }

        // ---- merge with partner half, rescale U, pack scaled P ----
#pragma unroll
        for (int c = 0; c < 4; c++) {
            float2 o0 = stats2[(c * 64 + m16 + gid) * 2 + (wh ^ 1)];
            float2 o1 = stats2[(c * 64 + m16 + gid + 8) * 2 + (wh ^ 1)];
            float mn0 = fmaxf(mrun[c][0], fmaxf(tmx[c][0], o0.x));
            float mn1 = fmaxf(mrun[c][1], fmaxf(tmx[c][1], o1.x));
            float corr0 = __expf(mrun[c][0] - mn0);
            float corr1 = __expf(mrun[c][1] - mn1);
            float f0 = __expf(tmx[c][0] - mn0);
            float f1 = __expf(tmx[c][1] - mn1);
            float g0 = __expf(o0.x - mn0);
            float g1 = __expf(o1.x - mn1);
            lrun[c][0] = lrun[c][0] * corr0 + tsum[c][0] * f0 + o0.y * g0;
            lrun[c][1] = lrun[c][1] * corr1 + tsum[c][1] * f1 + o1.y * g1;
            mrun[c][0] = mn0; mrun[c][1] = mn1;
#pragma unroll
            for (int nt = 0; nt < 4; nt++) {
                U[c][nt][0] *= corr0;
                U[c][nt][1] *= corr0;
                U[c][nt][2] *= corr1;
                U[c][nt][3] *= corr1;
            }
#pragma unroll
            for (int nt = 0; nt < 4; nt++) {
                int key = wh * 32 + nt * 8 + tig * 2;
                float p0 = sc[c][nt][0] * f0, p1 = sc[c][nt][1] * f0;
                u32 h01, l01;
                BFPACK(h01, p0, p1);
                float rx = p0 - __uint_as_float(h01 << 16);
                float ry = p1 - __uint_as_float(h01 & 0xffff0000u);
                BFPACK(l01, rx, ry);
                int ro = (c * 64 + m16 + gid) * STR + key;
                *(u32*)(sm + S_PH + ro) = h01;
                *(u32*)(sm + S_PL + ro) = l01;
                float p2 = sc[c][nt][2] * f1, p3 = sc[c][nt][3] * f1;
                BFPACK(h01, p2, p3);
                rx = p2 - __uint_as_float(h01 << 16);
                ry = p3 - __uint_as_float(h01 & 0xffff0000u);
                BFPACK(l01, rx, ry);
                ro = (c * 64 + m16 + gid + 8) * STR + key;
                *(u32*)(sm + S_PH + ro) = h01;
                *(u32*)(sm + S_PL + ro) = l01;
            }
        }
        __syncthreads();   // (b) P + K(t+1) + mask visible

        // ---- PV MMAs, term-major (U[c][nt] reuse distance 4) ----
#pragma unroll
        for (int c = 0; c < 4; c++) {
#pragma unroll
            for (int u = 0; u < 4; u++) {
                int ao = (c * 64 + m16 + gid) * STR + u * 16 + tig * 2;
                u32 pa0 = *(const u32*)(sm + S_PH + ao);
                u32 pa1 = *(const u32*)(sm + S_PH + ao + 8 * STR);
                u32 pa2 = *(const u32*)(sm + S_PH + ao + 8);
                u32 pa3 = *(const u32*)(sm + S_PH + ao + 8 * STR + 8);
                u32 la0 = *(const u32*)(sm + S_PL + ao);
                u32 la1 = *(const u32*)(sm + S_PL + ao + 8 * STR);
                u32 la2 = *(const u32*)(sm + S_PL + ao + 8);
                u32 la3 = *(const u32*)(sm + S_PL + ao + 8 * STR + 8);
                u32 vf[4][4];   // per nt: vh0, vh1, vl0, vl1 (sign applied)
#pragma unroll
                for (int nt = 0; nt < 4; nt++) {
                    int oc = wh * 2 + (nt >> 1);
                    int src = tsrc[c][oc];
                    u32 smask = (tsgn[c][oc] < 0) ? SGNM : 0u;
                    int bo = (src * 16 + (nt & 1) * 8 + gid) * STR + u * 16 + tig * 2;
                    vf[nt][0] = *(const u32*)(sm + S_VH + bo) ^ smask;
                    vf[nt][1] = *(const u32*)(sm + S_VH + bo + 8) ^ smask;
                    vf[nt][2] = *(const u32*)(sm + S_VL + bo) ^ smask;
                    vf[nt][3] = *(const u32*)(sm + S_VL + bo + 8) ^ smask;
                }
#pragma unroll
                for (int nt = 0; nt < 4; nt++)
                    HMMA(U[c][nt], pa0, pa1, pa2, pa3, vf[nt][0], vf[nt][1]);
#pragma unroll
                for (int nt = 0; nt < 4; nt++)
                    HMMA(U[c][nt], pa0, pa1, pa2, pa3, vf[nt][2], vf[nt][3]);
#pragma unroll
                for (int nt = 0; nt < 4; nt++)
                    HMMA(U[c][nt], la0, la1, la2, la3, vf[nt][0], vf[nt][1]);
            }
        }
        __syncthreads();   // (c) PV reads done before V overwrite

        // ---- store V(t+1); visibility ensured by next tile's syncs ----
        if (t < 15) {
#pragma unroll
            for (int i = 0; i < 4; i++) {
                int r = ldr + i * 16;
                kv_store_one(sm, S_VH, S_VL, r * STR + ldc, vR[i]);
            }
        }
    }

    // ---- register epilogue ----
    float inv[4][2];
#pragma unroll
    for (int c = 0; c < 4; c++) {
        inv[c][0] = 1.f / lrun[c][0];
        inv[c][1] = 1.f / lrun[c][1];
    }
    float* Og = g_O + (size_t)(b * SQ) * DM + h * DKH;
    int r0 = q0 + m16 + gid;
#pragma unroll
    for (int nt = 0; nt < 4; nt++) {
        int col = wh * 32 + nt * 8 + tig * 2;
        float o0 = 0.f, o1 = 0.f, o2 = 0.f, o3 = 0.f;
#pragma unroll
        for (int c = 0; c < 4; c++) {
            o0 += U[c][nt][0] * inv[c][0];
            o1 += U[c][nt][1] * inv[c][0];
            o2 += U[c][nt][2] * inv[c][1];
            o3 += U[c][nt][3] * inv[c][1];
        }
        *(float2*)(Og + (size_t)r0 * DM + col) = make_float2(o0, o1);
        *(float2*)(Og + (size_t)(r0 + 8) * DM + col) = make_float2(o2, o3);
    }
}

// ---------------------------------------------------------------------------
extern "C" void kernel_launch(void* const* d_in, const int* in_sizes, int n_in,
                              void* d_out, int out_size)
{
    (void)in_sizes; (void)n_in; (void)out_size;
    // 0 q, 1 k, 2 v, 3 mask, 4-19 weights, 20 bq, 21 bk, 22 bv, 23 bo
    WPtrs wp;
    for (int i = 0; i < 16; i++) wp.w[i] = (const float*)d_in[4 + i];

    build_wbig_kernel<<<dim3(32, 32, 4), 256>>>(wp);

    GemmArgs ga;
    for (int z = 0; z < 3; z++) {
        ga.A[z]    = (const float*)d_in[z];
        ga.bias[z] = (const float*)d_in[20 + z];
    }
    cudaFuncSetAttribute(qkv_gemm_kernel,
                         cudaFuncAttributeMaxDynamicSharedMemorySize, GEMM_SMEM_BYTES);
    cudaFuncSetAttribute(o_gemm_kernel,
                         cudaFuncAttributeMaxDynamicSharedMemorySize, GEMM_SMEM_BYTES);

    dim3 qkvgrid(DM / 128, MROWS / 128, 3);   // (8, 16, 3)
    qkv_gemm_kernel<<<qkvgrid, 256, GEMM_SMEM_BYTES>>>(ga);

    cudaFuncSetAttribute(quat_attn_tc_kernel,
                         cudaFuncAttributeMaxDynamicSharedMemorySize, ATT_SMEM_BYTES);
    quat_attn_tc_kernel<<<dim3(SQ / 64, BSZ * NH), 256, ATT_SMEM_BYTES>>>(
        (const int*)d_in[3]);

    dim3 ogrid(DM / 128, MROWS / 128);        // (8, 16)
    o_gemm_kernel<<<ogrid, 256, GEMM_SMEM_BYTES>>>((const float*)d_in[23], (float*)d_out);
}

// round 17
// speedup vs baseline: 1.0503x; 1.0174x over previous
#include <cuda_runtime.h>
#include <cuda_bf16.h>
#include <cstdint>
#include <math.h>

#define SQ   1024
#define DM   1024
#define NH   16
#define DKH  64
#define BSZ  2
#define MROWS (BSZ*SQ)

typedef uint32_t u32;

// ---------------------------------------------------------------------------
// Device scratch
// ---------------------------------------------------------------------------
__device__ __nv_bfloat16 g_Wth[4][DM*DM];  // W^T hi (K-major [n][k])
__device__ __nv_bfloat16 g_Wtl[4][DM*DM];  // W^T lo
__device__ float g_P[2][MROWS*DM];         // projected Q,K
__device__ float g_Vt[BSZ*NH*DKH*SQ];      // projected V, transposed [b,h,d,S]
__device__ float g_O[MROWS*DM];            // attention output

__constant__ int   c_SRC[16] = {0,1,2,3,  1,0,3,2,  2,3,0,1,  3,2,1,0};
__constant__ float c_SGN[16] = {1.f,1.f,1.f,1.f,  -1.f,1.f,-1.f,1.f,
                                -1.f,1.f,1.f,-1.f, -1.f,-1.f,1.f,1.f};

struct WPtrs { const float* w[16]; };
struct GemmArgs { const float* A[3]; const float* bias[3]; };

#define BFPACK(r, flo, fhi) \
    asm("cvt.rn.bf16x2.f32 %0, %1, %2;" : "=r"(r) : "f"(fhi), "f"(flo))

#define HMMA(c, a0, a1, a2, a3, b0, b1) \
    asm volatile("mma.sync.aligned.m16n8k16.row.col.f32.bf16.bf16.f32 " \
        "{%0,%1,%2,%3}, {%4,%5,%6,%7}, {%8,%9}, {%0,%1,%2,%3};" \
        : "+f"((c)[0]), "+f"((c)[1]), "+f"((c)[2]), "+f"((c)[3]) \
        : "r"(a0), "r"(a1), "r"(a2), "r"(a3), "r"(b0), "r"(b1))

#define SGNM 0x80008000u

// ---------------------------------------------------------------------------
__global__ __launch_bounds__(256)
void build_wbig_kernel(WPtrs p) {
    __shared__ float s[32][33];
    int tx = threadIdx.x & 31, ty = threadIdx.x >> 5;
    int k0 = blockIdx.x * 32, n0 = blockIdx.y * 32, which = blockIdx.z;
    int rb = k0 >> 8, cb = n0 >> 8;
    float sgn = c_SGN[rb * 4 + cb];
    const float* src = p.w[which * 4 + c_SRC[rb * 4 + cb]];
#pragma unroll
    for (int i = 0; i < 4; i++) {
        int kl = ty + i * 8;
        s[kl][tx] = sgn * src[((k0 + kl) & 255) * 256 + ((n0 + tx) & 255)];
    }
    __syncthreads();
#pragma unroll
    for (int i = 0; i < 4; i++) {
        int nl = ty + i * 8;
        float v = s[tx][nl];
        __nv_bfloat16 hi = __float2bfloat16_rn(v);
        __nv_bfloat16 lo = __float2bfloat16_rn(v - __bfloat162float(hi));
        size_t o = (size_t)(n0 + nl) * DM + k0 + tx;
        g_Wth[which][o] = hi;
        g_Wtl[which][o] = lo;
    }
}

// ---------------------------------------------------------------------------
// Tensor-core GEMM: 128x128 tile, 512 threads (16 warps = 4 warps/SMSP),
// double-buffered smem.
// ---------------------------------------------------------------------------
#define KCP 40
#define GST (128 * KCP)
#define GEMM_SMEM_BYTES (2 * 4 * GST * 2)  // 81920 B

__device__ __forceinline__
void gemm_store_stage(__nv_bfloat16* base, int tid,
                      const float4 aR[2], const uint4 whR, const uint4 wlR)
{
    __nv_bfloat16* Ah_s = base;
    __nv_bfloat16* Al_s = base + GST;
    __nv_bfloat16* Wh_s = base + 2 * GST;
    __nv_bfloat16* Wl_s = base + 3 * GST;
#pragma unroll
    for (int i = 0; i < 2; i++) {
        int idx = tid + i * 512;
        int r = idx >> 3, c4 = (idx & 7) * 4;
        float4 a = aR[i];
        u32 h01, h23, l01, l23;
        BFPACK(h01, a.x, a.y);
        BFPACK(h23, a.z, a.w);
        float rx = a.x - __uint_as_float(h01 << 16);
        float ry = a.y - __uint_as_float(h01 & 0xffff0000u);
        float rz = a.z - __uint_as_float(h23 << 16);
        float rw = a.w - __uint_as_float(h23 & 0xffff0000u);
        BFPACK(l01, rx, ry);
        BFPACK(l23, rz, rw);
        int so = r * KCP + c4;
        *(uint2*)(Ah_s + so) = make_uint2(h01, h23);
        *(uint2*)(Al_s + so) = make_uint2(l01, l23);
    }
    {
        int r = tid >> 2, c8 = (tid & 3) * 8;   // 128 rows x 4 uint4
        int so = r * KCP + c8;
        *(uint4*)(Wh_s + so) = whR;
        *(uint4*)(Wl_s + so) = wlR;
    }
}

__device__ __forceinline__
void tc_gemm_body(__nv_bfloat16* gsm, const float* __restrict__ A,
                  const __nv_bfloat16* __restrict__ Wh,
                  const __nv_bfloat16* __restrict__ Wl,
                  const float* __restrict__ bias, float* __restrict__ C, int vt)
{
    int tid = threadIdx.x;
    int wid = tid >> 5, lane = tid & 31;
    int gid = lane >> 2, tig = lane & 3;
    int wm = wid & 3, wn = wid >> 2;         // 4(m) x 4(n) warps, tile 32x32
    int m0 = blockIdx.y * 128, n0 = blockIdx.x * 128;

    float acc[2][4][4];
#pragma unroll
    for (int mi = 0; mi < 2; mi++)
#pragma unroll
        for (int ni = 0; ni < 4; ni++)
#pragma unroll
            for (int j = 0; j < 4; j++) acc[mi][ni][j] = 0.f;

    int wr = tid >> 2, wc8 = (tid & 3) * 8;  // W load coords

    float4 aR[2]; uint4 whR, wlR;
    {
        const float* Ar = A + (size_t)m0 * DM;
#pragma unroll
        for (int i = 0; i < 2; i++) {
            int idx = tid + i * 512;
            int r = idx >> 3, c4 = (idx & 7) * 4;
            aR[i] = *(const float4*)(Ar + (size_t)r * DM + c4);
        }
        size_t go = (size_t)(n0 + wr) * DM + wc8;
        whR = *(const uint4*)(Wh + go);
        wlR = *(const uint4*)(Wl + go);
    }
    gemm_store_stage(gsm, tid, aR, whR, wlR);
    __syncthreads();

    for (int kt = 0; kt < 32; kt++) {
        if (kt < 31) {
            int k0n = (kt + 1) * 32;
            const float* Ar = A + (size_t)m0 * DM + k0n;
#pragma unroll
            for (int i = 0; i < 2; i++) {
                int idx = tid + i * 512;
                int r = idx >> 3, c4 = (idx & 7) * 4;
                aR[i] = *(const float4*)(Ar + (size_t)r * DM + c4);
            }
            size_t go = (size_t)(n0 + wr) * DM + k0n + wc8;
            whR = *(const uint4*)(Wh + go);
            wlR = *(const uint4*)(Wl + go);
        }

        __nv_bfloat16* st = gsm + (size_t)(kt & 1) * 4 * GST;
        __nv_bfloat16* Ah_s = st;
        __nv_bfloat16* Al_s = st + GST;
        __nv_bfloat16* Wh_s = st + 2 * GST;
        __nv_bfloat16* Wl_s = st + 3 * GST;

#pragma unroll
        for (int ks = 0; ks < 2; ks++) {
            int kb = ks * 16 + tig * 2;
            u32 bh[4][2], bl[4][2];
#pragma unroll
            for (int ni = 0; ni < 4; ni++) {
                int n = wn * 32 + ni * 8 + gid;
                int off = n * KCP + kb;
                bh[ni][0] = *(const u32*)(Wh_s + off);
                bh[ni][1] = *(const u32*)(Wh_s + off + 8);
                bl[ni][0] = *(const u32*)(Wl_s + off);
                bl[ni][1] = *(const u32*)(Wl_s + off + 8);
            }
            u32 ah[2][4], al[2][4];
#pragma unroll
            for (int mi = 0; mi < 2; mi++) {
                int r = wm * 32 + mi * 16 + gid;
                int off = r * KCP + kb;
                ah[mi][0] = *(const u32*)(Ah_s + off);
                ah[mi][1] = *(const u32*)(Ah_s + off + 8 * KCP);
                ah[mi][2] = *(const u32*)(Ah_s + off + 8);
                ah[mi][3] = *(const u32*)(Ah_s + off + 8 * KCP + 8);
                al[mi][0] = *(const u32*)(Al_s + off);
                al[mi][1] = *(const u32*)(Al_s + off + 8 * KCP);
                al[mi][2] = *(const u32*)(Al_s + off + 8);
                al[mi][3] = *(const u32*)(Al_s + off + 8 * KCP + 8);
            }
#pragma unroll
            for (int mi = 0; mi < 2; mi++)
#pragma unroll
                for (int ni = 0; ni < 4; ni++)
                    HMMA(acc[mi][ni], ah[mi][0], ah[mi][1], ah[mi][2], ah[mi][3],
                         bh[ni][0], bh[ni][1]);
#pragma unroll
            for (int mi = 0; mi < 2; mi++)
#pragma unroll
                for (int ni = 0; ni < 4; ni++)
                    HMMA(acc[mi][ni], ah[mi][0], ah[mi][1], ah[mi][2], ah[mi][3],
                         bl[ni][0], bl[ni][1]);
#pragma unroll
            for (int mi = 0; mi < 2; mi++)
#pragma unroll
                for (int ni = 0; ni < 4; ni++)
                    HMMA(acc[mi][ni], al[mi][0], al[mi][1], al[mi][2], al[mi][3],
                         bh[ni][0], bh[ni][1]);
        }
        if (kt < 31)
            gemm_store_stage(gsm + (size_t)((kt + 1) & 1) * 4 * GST, tid, aR, whR, wlR);
        __syncthreads();
    }

#pragma unroll
    for (int mi = 0; mi < 2; mi++) {
        int r = m0 + wm * 32 + mi * 16 + gid;
#pragma unroll
        for (int ni = 0; ni < 4; ni++) {
            int c = n0 + wn * 32 + ni * 8 + tig * 2;
            float b0 = bias[c], b1 = bias[c + 1];
            if (!vt) {
                *(float2*)(C + (size_t)r * DM + c) =
                    make_float2(acc[mi][ni][0] + b0, acc[mi][ni][1] + b1);
                *(float2*)(C + (size_t)(r + 8) * DM + c) =
                    make_float2(acc[mi][ni][2] + b0, acc[mi][ni][3] + b1);
            } else {
                int b = r >> 10, s = r & 1023;
                int h = c >> 6, d = c & 63;
                float* base = g_Vt + ((size_t)(b * NH + h) * DKH) * SQ;
                base[(size_t)d * SQ + s]           = acc[mi][ni][0] + b0;
                base[(size_t)(d + 1) * SQ + s]     = acc[mi][ni][1] + b1;
                base[(size_t)d * SQ + s + 8]       = acc[mi][ni][2] + b0;
                base[(size_t)(d + 1) * SQ + s + 8] = acc[mi][ni][3] + b1;
            }
        }
    }
}

__global__ __launch_bounds__(512, 1)
void qkv_gemm_kernel(GemmArgs args) {
    extern __shared__ __nv_bfloat16 gsm[];
    int z = blockIdx.z;
    tc_gemm_body(gsm, args.A[z], g_Wth[z], g_Wtl[z], args.bias[z],
                 z < 2 ? g_P[z] : nullptr, z == 2);
}
__global__ __launch_bounds__(512, 1)
void o_gemm_kernel(const float* __restrict__ bias, float* __restrict__ Cout) {
    extern __shared__ __nv_bfloat16 gsm[];
    tc_gemm_body(gsm, g_O, g_Wth[3], g_Wtl[3], bias, Cout, 0);
}

// ---------------------------------------------------------------------------
// Tensor-core quaternion flash attention (R16 version, unchanged).
// ---------------------------------------------------------------------------
#define STR 72
#define TILE_B (64*STR)

#define S_QH  0
#define S_QL  (S_QH + TILE_B)
#define S_KH  (S_QL + TILE_B)
#define S_KL  (S_KH + TILE_B)
#define S_VH  (S_KL + TILE_B)
#define S_VL  (S_VH + TILE_B)
#define S_PH  (S_VL + TILE_B)           // [4][64][STR]
#define S_PL  (S_PH + 4*TILE_B)
#define S_END (S_PL + 4*TILE_B)
#define ATT_SMEM_BYTES (S_END*2 + 4*64*2*8 + 256)

__device__ __forceinline__
void kv_store_one(__nv_bfloat16* sm, int hioff, int looff, int so, float4 a)
{
    u32 h01, h23, l01, l23;
    BFPACK(h01, a.x, a.y);
    BFPACK(h23, a.z, a.w);
    float rx = a.x - __uint_as_float(h01 << 16);
    float ry = a.y - __uint_as_float(h01 & 0xffff0000u);
    float rz = a.z - __uint_as_float(h23 << 16);
    float rw = a.w - __uint_as_float(h23 & 0xffff0000u);
    BFPACK(l01, rx, ry);
    BFPACK(l23, rz, rw);
    *(uint2*)(sm + hioff + so) = make_uint2(h01, h23);
    *(uint2*)(sm + looff + so) = make_uint2(l01, l23);
}

__global__ __launch_bounds__(256, 1)
void quat_attn_tc_kernel(const int* __restrict__ mask)
{
    extern __shared__ __nv_bfloat16 sm[];
    float2* stats2 = (float2*)(sm + S_END);     // [4][64][2] (max, expsum)
    int*    msk    = (int*)(stats2 + 4 * 64 * 2);

    const int tsrc[4][4] = {{0,1,2,3},{1,0,3,2},{2,3,0,1},{3,2,1,0}};
    const int tsgn[4][4] = {{1,1,1,1},{-1,1,-1,1},{-1,1,1,-1},{-1,-1,1,1}};

    int tid = threadIdx.x;
    int wid = tid >> 5, lane = tid & 31;
    int gid = lane >> 2, tig = lane & 3;
    int mtile = wid >> 1, wh = wid & 1;
    int m16 = mtile * 16;
    int bh = blockIdx.y;
    int b = bh >> 4, h = bh & 15;
    int q0 = blockIdx.x * 64;

    const float* Qg = g_P[0] + (size_t)(b * SQ) * DM + h * DKH;
    const float* Kg = g_P[1] + (size_t)(b * SQ) * DM + h * DKH;
    const float* Vg = g_Vt + (size_t)bh * DKH * SQ;
    const int*   mrow = mask + b * SQ;

    int ldr = tid >> 4, ldc = (tid & 15) * 4;

    // ---- load Q tile (scaled by 1/8) ----
#pragma unroll
    for (int i = 0; i < 4; i++) {
        int r = ldr + i * 16;
        float4 a = *(const float4*)(Qg + (size_t)(q0 + r) * DM + ldc);
        a.x *= 0.125f; a.y *= 0.125f; a.z *= 0.125f; a.w *= 0.125f;
        kv_store_one(sm, S_QH, S_QL, r * STR + ldc, a);
    }
    __syncthreads();

    // ---- persistent Q fragments ----
    u32 qfh[4][4], qfl[4][4];
#pragma unroll
    for (int u = 0; u < 4; u++) {
        int off = (m16 + gid) * STR + u * 16 + tig * 2;
        qfh[u][0] = *(const u32*)(sm + S_QH + off);
        qfh[u][1] = *(const u32*)(sm + S_QH + off + 8 * STR);
        qfh[u][2] = *(const u32*)(sm + S_QH + off + 8);
        qfh[u][3] = *(const u32*)(sm + S_QH + off + 8 * STR + 8);
        qfl[u][0] = *(const u32*)(sm + S_QL + off);
        qfl[u][1] = *(const u32*)(sm + S_QL + off + 8 * STR);
        qfl[u][2] = *(const u32*)(sm + S_QL + off + 8);
        qfl[u][3] = *(const u32*)(sm + S_QL + off + 8 * STR + 8);
    }

    float mrun[4][2], lrun[4][2];
    float U[4][4][4];
#pragma unroll
    for (int c = 0; c < 4; c++) {
#pragma unroll
        for (int j = 0; j < 2; j++) { mrun[c][j] = -1e30f; lrun[c][j] = 0.f; }
#pragma unroll
        for (int nt = 0; nt < 4; nt++)
#pragma unroll
            for (int j = 0; j < 4; j++) U[c][nt][j] = 0.f;
    }

    float4 kR[4], vR[4];
#pragma unroll
    for (int i = 0; i < 4; i++) {
        int r = ldr + i * 16;
        kR[i] = *(const float4*)(Kg + (size_t)r * DM + ldc);
        vR[i] = *(const float4*)(Vg + (size_t)r * SQ + ldc);
    }
#pragma unroll
    for (int i = 0; i < 4; i++) {
        int r = ldr + i * 16;
        kv_store_one(sm, S_KH, S_KL, r * STR + ldc, kR[i]);
        kv_store_one(sm, S_VH, S_VL, r * STR + ldc, vR[i]);
    }
    if (tid < 64) msk[tid] = mrow[tid];
    __syncthreads();

    for (int t = 0; t < 16; t++) {
        int n0 = t * 64;
        if (t < 15) {
            int n1 = n0 + 64;
#pragma unroll
            for (int i = 0; i < 4; i++) {
                int r = ldr + i * 16;
                kR[i] = *(const float4*)(Kg + (size_t)(n1 + r) * DM + ldc);
                vR[i] = *(const float4*)(Vg + (size_t)r * SQ + n1 + ldc);
            }
        }

        // ---- score MMAs, term-major ----
        float sc[4][4][4];
#pragma unroll
        for (int c = 0; c < 4; c++)
#pragma unroll
            for (int nt = 0; nt < 4; nt++)
#pragma unroll
                for (int j = 0; j < 4; j++) sc[c][nt][j] = 0.f;

#pragma unroll
        for (int nt = 0; nt < 4; nt++) {
            int kb0 = wh * 32 + nt * 8;
            u32 kf[4][2][2];
#pragma unroll
            for (int comp = 0; comp < 4; comp++) {
                int off = (kb0 + gid) * STR + comp * 16 + tig * 2;
                kf[comp][0][0] = *(const u32*)(sm + S_KH + off);
                kf[comp][0][1] = *(const u32*)(sm + S_KH + off + 8);
                kf[comp][1][0] = *(const u32*)(sm + S_KL + off);
                kf[comp][1][1] = *(const u32*)(sm + S_KL + off + 8);
            }
#pragma unroll
            for (int u = 0; u < 4; u++)
#pragma unroll
                for (int c = 0; c < 4; c++) {
                    int src = tsrc[u][c];
                    u32 s = (tsgn[u][c] < 0) ? SGNM : 0u;
                    HMMA(sc[c][nt], qfh[u][0], qfh[u][1], qfh[u][2], qfh[u][3],
                         kf[src][0][0] ^ s, kf[src][0][1] ^ s);
                }
#pragma unroll
            for (int u = 0; u < 4; u++)
#pragma unroll
                for (int c = 0; c < 4; c++) {
                    int src = tsrc[u][c];
                    u32 s = (tsgn[u][c] < 0) ? SGNM : 0u;
                    HMMA(sc[c][nt], qfh[u][0], qfh[u][1], qfh[u][2], qfh[u][3],
                         kf[src][1][0] ^ s, kf[src][1][1] ^ s);
                }
#pragma unroll
            for (int u = 0; u < 4; u++)
#pragma unroll
                for (int c = 0; c < 4; c++) {
                    int src = tsrc[u][c];
                    u32 s = (tsgn[u][c] < 0) ? SGNM : 0u;
                    HMMA(sc[c][nt], qfl[u][0], qfl[u][1], qfl[u][2], qfl[u][3],
                         kf[src][0][0] ^ s, kf[src][0][1] ^ s);
                }
        }

        // ---- mask ----
#pragma unroll
        for (int nt = 0; nt < 4; nt++) {
            int kb0 = wh * 32 + nt * 8 + tig * 2;
            int m0v = msk[kb0], m1v = msk[kb0 + 1];
#pragma unroll
            for (int c = 0; c < 4; c++) {
                if (!m0v) { sc[c][nt][0] = -1e9f; sc[c][nt][2] = -1e9f; }
                if (!m1v) { sc[c][nt][1] = -1e9f; sc[c][nt][3] = -1e9f; }
            }
        }

        // ---- per-warp tile softmax, single exchange ----
        float tmx[4][2], tsum[4][2];
#pragma unroll
        for (int c = 0; c < 4; c++) {
            float t0 = -1e30f, t1 = -1e30f;
#pragma unroll
            for (int nt = 0; nt < 4; nt++) {
                t0 = fmaxf(t0, fmaxf(sc[c][nt][0], sc[c][nt][1]));
                t1 = fmaxf(t1, fmaxf(sc[c][nt][2], sc[c][nt][3]));
            }
            t0 = fmaxf(t0, __shfl_xor_sync(0xffffffffu, t0, 1));
            t0 = fmaxf(t0, __shfl_xor_sync(0xffffffffu, t0, 2));
            t1 = fmaxf(t1, __shfl_xor_sync(0xffffffffu, t1, 1));
            t1 = fmaxf(t1, __shfl_xor_sync(0xffffffffu, t1, 2));
            float s0 = 0.f, s1 = 0.f;
#pragma unroll
            for (int nt = 0; nt < 4; nt++) {
                sc[c][nt][0] = __expf(sc[c][nt][0] - t0);
                sc[c][nt][1] = __expf(sc[c][nt][1] - t0);
                sc[c][nt][2] = __expf(sc[c][nt][2] - t1);
                sc[c][nt][3] = __expf(sc[c][nt][3] - t1);
                s0 += sc[c][nt][0] + sc[c][nt][1];
                s1 += sc[c][nt][2] + sc[c][nt][3];
            }
            s0 += __shfl_xor_sync(0xffffffffu, s0, 1);
            s0 += __shfl_xor_sync(0xffffffffu, s0, 2);
            s1 += __shfl_xor_sync(0xffffffffu, s1, 1);
            s1 += __shfl_xor_sync(0xffffffffu, s1, 2);
            tmx[c][0] = t0; tmx[c][1] = t1;
            tsum[c][0] = s0; tsum[c][1] = s1;
            if (tig == 0) {
                stats2[(c * 64 + m16 + gid) * 2 + wh] = make_float2(t0, s0);
                stats2[(c * 64 + m16 + gid + 8) * 2 + wh] = make_float2(t1, s1);
            }
        }
        __syncthreads();   // (a)

        // ---- store K(t+1)+mask into smem ----
        if (t < 15) {
#pragma unroll
            for (int i = 0; i < 4; i++) {
                int r = ldr + i * 16;
                kv_store_one(sm, S_KH, S_KL, r * STR + ldc, kR[i]);
            }
            if (tid < 64) msk[tid] = mrow[n0 + 64 + tid];
        }

        // ---- merge with partner half, rescale U, pack scaled P ----
#pragma unroll
        for (int c = 0; c < 4; c++) {
            float2 o0 = stats2[(c * 64 + m16 + gid) * 2 + (wh ^ 1)];
            float2 o1 = stats2[(c * 64 + m16 + gid + 8) * 2 + (wh ^ 1)];
            float mn0 = fmaxf(mrun[c][0], fmaxf(tmx[c][0], o0.x));
            float mn1 = fmaxf(mrun[c][1], fmaxf(tmx[c][1], o1.x));
            float corr0 = __expf(mrun[c][0] - mn0);
            float corr1 = __expf(mrun[c][1] - mn1);
            float f0 = __expf(tmx[c][0] - mn0);
            float f1 = __expf(tmx[c][1] - mn1);
            float g0 = __expf(o0.x - mn0);
            float g1 = __expf(o1.x - mn1);
            lrun[c][0] = lrun[c][0] * corr0 + tsum[c][0] * f0 + o0.y * g0;
            lrun[c][1] = lrun[c][1] * corr1 + tsum[c][1] * f1 + o1.y * g1;
            mrun[c][0] = mn0; mrun[c][1] = mn1;
#pragma unroll
            for (int nt = 0; nt < 4; nt++) {
                U[c][nt][0] *= corr0;
                U[c][nt][1] *= corr0;
                U[c][nt][2] *= corr1;
                U[c][nt][3] *= corr1;
            }
#pragma unroll
            for (int nt = 0; nt < 4; nt++) {
                int key = wh * 32 + nt * 8 + tig * 2;
                float p0 = sc[c][nt][0] * f0, p1 = sc[c][nt][1] * f0;
                u32 h01, l01;
                BFPACK(h01, p0, p1);
                float rx = p0 - __uint_as_float(h01 << 16);
                float ry = p1 - __uint_as_float(h01 & 0xffff0000u);
                BFPACK(l01, rx, ry);
                int ro = (c * 64 + m16 + gid) * STR + key;
                *(u32*)(sm + S_PH + ro) = h01;
                *(u32*)(sm + S_PL + ro) = l01;
                float p2 = sc[c][nt][2] * f1, p3 = sc[c][nt][3] * f1;
                BFPACK(h01, p2, p3);
                rx = p2 - __uint_as_float(h01 << 16);
                ry = p3 - __uint_as_float(h01 & 0xffff0000u);
                BFPACK(l01, rx, ry);
                ro = (c * 64 + m16 + gid + 8) * STR + key;
                *(u32*)(sm + S_PH + ro) = h01;
                *(u32*)(sm + S_PL + ro) = l01;
            }
        }
        __syncthreads();   // (b)

        // ---- PV MMAs, term-major ----
#pragma unroll
        for (int c = 0; c < 4; c++) {
#pragma unroll
            for (int u = 0; u < 4; u++) {
                int ao = (c * 64 + m16 + gid) * STR + u * 16 + tig * 2;
                u32 pa0 = *(const u32*)(sm + S_PH + ao);
                u32 pa1 = *(const u32*)(sm + S_PH + ao + 8 * STR);
                u32 pa2 = *(const u32*)(sm + S_PH + ao + 8);
                u32 pa3 = *(const u32*)(sm + S_PH + ao + 8 * STR + 8);
                u32 la0 = *(const u32*)(sm + S_PL + ao);
                u32 la1 = *(const u32*)(sm + S_PL + ao + 8 * STR);
                u32 la2 = *(const u32*)(sm + S_PL + ao + 8);
                u32 la3 = *(const u32*)(sm + S_PL + ao + 8 * STR + 8);
                u32 vf[4][4];
#pragma unroll
                for (int nt = 0; nt < 4; nt++) {
                    int oc = wh * 2 + (nt >> 1);
                    int src = tsrc[c][oc];
                    u32 smask = (tsgn[c][oc] < 0) ? SGNM : 0u;
                    int bo = (src * 16 + (nt & 1) * 8 + gid) * STR + u * 16 + tig * 2;
                    vf[nt][0] = *(const u32*)(sm + S_VH + bo) ^ smask;
                    vf[nt][1] = *(const u32*)(sm + S_VH + bo + 8) ^ smask;
                    vf[nt][2] = *(const u32*)(sm + S_VL + bo) ^ smask;
                    vf[nt][3] = *(const u32*)(sm + S_VL + bo + 8) ^ smask;
                }
#pragma unroll
                for (int nt = 0; nt < 4; nt++)
                    HMMA(U[c][nt], pa0, pa1, pa2, pa3, vf[nt][0], vf[nt][1]);
#pragma unroll
                for (int nt = 0; nt < 4; nt++)
                    HMMA(U[c][nt], pa0, pa1, pa2, pa3, vf[nt][2], vf[nt][3]);
#pragma unroll
                for (int nt = 0; nt < 4; nt++)
                    HMMA(U[c][nt], la0, la1, la2, la3, vf[nt][0], vf[nt][1]);
            }
        }
        __syncthreads();   // (c)

        // ---- store V(t+1) ----
        if (t < 15) {
#pragma unroll
            for (int i = 0; i < 4; i++) {
                int r = ldr + i * 16;
                kv_store_one(sm, S_VH, S_VL, r * STR + ldc, vR[i]);
            }
        }
    }

    // ---- register epilogue ----
    float inv[4][2];
#pragma unroll
    for (int c = 0; c < 4; c++) {
        inv[c][0] = 1.f / lrun[c][0];
        inv[c][1] = 1.f / lrun[c][1];
    }
    float* Og = g_O + (size_t)(b * SQ) * DM + h * DKH;
    int r0 = q0 + m16 + gid;
#pragma unroll
    for (int nt = 0; nt < 4; nt++) {
        int col = wh * 32 + nt * 8 + tig * 2;
        float o0 = 0.f, o1 = 0.f, o2 = 0.f, o3 = 0.f;
#pragma unroll
        for (int c = 0; c < 4; c++) {
            o0 += U[c][nt][0] * inv[c][0];
            o1 += U[c][nt][1] * inv[c][0];
            o2 += U[c][nt][2] * inv[c][1];
            o3 += U[c][nt][3] * inv[c][1];
        }
        *(float2*)(Og + (size_t)r0 * DM + col) = make_float2(o0, o1);
        *(float2*)(Og + (size_t)(r0 + 8) * DM + col) = make_float2(o2, o3);
    }
}

// ---------------------------------------------------------------------------
extern "C" void kernel_launch(void* const* d_in, const int* in_sizes, int n_in,
                              void* d_out, int out_size)
{
    (void)in_sizes; (void)n_in; (void)out_size;
    // 0 q, 1 k, 2 v, 3 mask, 4-19 weights, 20 bq, 21 bk, 22 bv, 23 bo
    WPtrs wp;
    for (int i = 0; i < 16; i++) wp.w[i] = (const float*)d_in[4 + i];

    build_wbig_kernel<<<dim3(32, 32, 4), 256>>>(wp);

    GemmArgs ga;
    for (int z = 0; z < 3; z++) {
        ga.A[z]    = (const float*)d_in[z];
        ga.bias[z] = (const float*)d_in[20 + z];
    }
    cudaFuncSetAttribute(qkv_gemm_kernel,
                         cudaFuncAttributeMaxDynamicSharedMemorySize, GEMM_SMEM_BYTES);
    cudaFuncSetAttribute(o_gemm_kernel,
                         cudaFuncAttributeMaxDynamicSharedMemorySize, GEMM_SMEM_BYTES);

    dim3 qkvgrid(DM / 128, MROWS / 128, 3);   // (8, 16, 3)
    qkv_gemm_kernel<<<qkvgrid, 512, GEMM_SMEM_BYTES>>>(ga);

    cudaFuncSetAttribute(quat_attn_tc_kernel,
                         cudaFuncAttributeMaxDynamicSharedMemorySize, ATT_SMEM_BYTES);
    quat_attn_tc_kernel<<<dim3(SQ / 64, BSZ * NH), 256, ATT_SMEM_BYTES>>>(
        (const int*)d_in[3]);

    dim3 ogrid(DM / 128, MROWS / 128);        // (8, 16)
    o_gemm_kernel<<<ogrid, 512, GEMM_SMEM_BYTES>>>((const float*)d_in[23], (float*)d_out);
}